// round 2
// baseline (speedup 1.0000x reference)
#include <cuda_runtime.h>
#include <cstdint>

#define B_    4
#define N_    2048
#define DIM_  384
#define H_    8
#define HD_   48
#define HID_  1024
#define M_    (B_*N_)          // 8192
#define SCALE_ 0.14433756729740643f   // 48^-0.5
#define EPS_   1e-5f

// ---------------- scratch (no allocation allowed; __device__ globals) ----------
__device__ float g_xa [M_*DIM_];
__device__ float g_Q  [M_*DIM_];   // [B,H,N,HD]
__device__ float g_K  [M_*DIM_];
__device__ float g_V  [M_*DIM_];
__device__ float g_O  [M_*DIM_];   // [B,N,H*HD]
__device__ float g_h  [M_*DIM_];
__device__ float g_hf [M_*DIM_];
__device__ float g_gb [M_*HID_];

// ---------------- RMSNorm: one row (384) per block of 128 threads --------------
__global__ void rmsnorm_kernel(const float* __restrict__ src,
                               const float* __restrict__ w,
                               float* __restrict__ dst) {
    const int row = blockIdx.x;
    const int tid = threadIdx.x;
    const float* xr = src + row*DIM_;
    float v0 = xr[tid], v1 = xr[tid+128], v2 = xr[tid+256];
    float s = v0*v0 + v1*v1 + v2*v2;
    #pragma unroll
    for (int o = 16; o > 0; o >>= 1) s += __shfl_xor_sync(0xffffffffu, s, o);
    __shared__ float red[4];
    if ((tid & 31) == 0) red[tid >> 5] = s;
    __syncthreads();
    float tot = red[0] + red[1] + red[2] + red[3];
    float sc = rsqrtf(tot * (1.0f/DIM_) + EPS_);
    float* dr = dst + row*DIM_;
    dr[tid]     = v0*sc*w[tid];
    dr[tid+128] = v1*sc*w[tid+128];
    dr[tid+256] = v2*sc*w[tid+256];
}

// ---------------- generic tiled fp32 GEMM: C = A[M,K] * W[N,K]^T ---------------
// 128x128 tile, BK=16, 256 threads, 8x8 microtile. Epilogue selected by MODE.
#define MODE_QKV   1
#define MODE_PROJ  2
#define MODE_SILU  3
#define MODE_MUL   4
#define MODE_FINAL 5

template<int KDIM, int MODE>
__global__ void __launch_bounds__(256, 2) gemm_kernel(
    const float* __restrict__ A, const float* __restrict__ W,
    float* __restrict__ C,
    const float* __restrict__ aux1,   // pos | b_proj | - | - | -
    const float* __restrict__ aux2,   // -   | x      | - | - | h
    const int* __restrict__ npts)     // int32 (jax canonicalizes int64 -> int32)
{
    __shared__ float As[16][132];
    __shared__ float Bs[16][132];
    const int tid = threadIdx.x;
    const int bm = blockIdx.y << 7;
    const int bn = blockIdx.x << 7;
    const int tx = (tid & 15) << 3;
    const int ty = (tid >> 4) << 3;
    const int lr = tid >> 2;          // 0..63
    const int lc = (tid & 3) << 2;    // 0,4,8,12

    float acc[8][8];
    #pragma unroll
    for (int i = 0; i < 8; i++)
        #pragma unroll
        for (int j = 0; j < 8; j++) acc[i][j] = 0.f;

    const float* Ap = A + (long long)(bm + lr)*KDIM + lc;
    const float* Wp = W + (long long)(bn + lr)*KDIM + lc;

    for (int k0 = 0; k0 < KDIM; k0 += 16) {
        float4 a0 = *(const float4*)(Ap + k0);
        float4 a1 = *(const float4*)(Ap + (long long)64*KDIM + k0);
        float4 b0 = *(const float4*)(Wp + k0);
        float4 b1 = *(const float4*)(Wp + (long long)64*KDIM + k0);
        __syncthreads();
        As[lc+0][lr]    = a0.x; As[lc+1][lr]    = a0.y; As[lc+2][lr]    = a0.z; As[lc+3][lr]    = a0.w;
        As[lc+0][lr+64] = a1.x; As[lc+1][lr+64] = a1.y; As[lc+2][lr+64] = a1.z; As[lc+3][lr+64] = a1.w;
        Bs[lc+0][lr]    = b0.x; Bs[lc+1][lr]    = b0.y; Bs[lc+2][lr]    = b0.z; Bs[lc+3][lr]    = b0.w;
        Bs[lc+0][lr+64] = b1.x; Bs[lc+1][lr+64] = b1.y; Bs[lc+2][lr+64] = b1.z; Bs[lc+3][lr+64] = b1.w;
        __syncthreads();
        #pragma unroll
        for (int kk = 0; kk < 16; kk++) {
            float a[8], b[8];
            #pragma unroll
            for (int i = 0; i < 8; i++) a[i] = As[kk][ty + i];
            #pragma unroll
            for (int j = 0; j < 8; j++) b[j] = Bs[kk][tx + j];
            #pragma unroll
            for (int i = 0; i < 8; i++)
                #pragma unroll
                for (int j = 0; j < 8; j++)
                    acc[i][j] += a[i] * b[j];
        }
    }

    #pragma unroll
    for (int i = 0; i < 8; i++) {
        const int m = bm + ty + i;
        #pragma unroll
        for (int j = 0; j < 8; j++) {
            const int n = bn + tx + j;
            float v = acc[i][j];
            if constexpr (MODE == MODE_QKV) {
                const int b   = m >> 11;
                const int ns  = m & 2047;
                const int part = n / DIM_;
                const int rem  = n - part*DIM_;
                const int hh   = rem / HD_;
                const int hd   = rem - hh*HD_;
                if (part < 2) v += aux1[(b*N_ + ns)*HD_ + hd];
                float* dst = (part == 0) ? g_Q : (part == 1 ? g_K : g_V);
                dst[(((b << 3) + hh)*N_ + ns)*HD_ + hd] = v;
            } else if constexpr (MODE == MODE_PROJ) {
                C[m*DIM_ + n] = v + aux1[n] + aux2[m*DIM_ + n];
            } else if constexpr (MODE == MODE_SILU) {
                C[m*HID_ + n] = v / (1.0f + __expf(-v));
            } else if constexpr (MODE == MODE_MUL) {
                C[m*HID_ + n] *= v;
            } else if constexpr (MODE == MODE_FINAL) {
                const int np = npts[m >> 11];
                C[m*DIM_ + n] = ((m & 2047) < np)
                                ? (aux2[m*DIM_ + n] + v) : 0.0f;
            }
        }
    }
}

// ---------------- flash attention: block = (bh, 64-row q tile) -----------------
// smem: Qs/Ks/Vs [64][52] (padded), Ms/Ps [64][68] (padded). online softmax.
#define QKV_STRIDE 52
#define MP_STRIDE  68
#define ATTN_SMEM_BYTES ((3*64*QKV_STRIDE + 2*64*MP_STRIDE) * 4)

__global__ void __launch_bounds__(256, 2) attn_kernel(const float* __restrict__ mask) {
    extern __shared__ float sm[];
    float* Qs = sm;
    float* Ks = sm + 64*QKV_STRIDE;
    float* Vs = sm + 2*64*QKV_STRIDE;
    float* Ms = sm + 3*64*QKV_STRIDE;
    float* Ps = Ms + 64*MP_STRIDE;

    const int bh  = blockIdx.y;          // b*8 + h
    const int b   = bh >> 3;
    const int hh  = bh & 7;
    const int q0  = blockIdx.x * 64;
    const int tid = threadIdx.x;
    const int r   = tid >> 2;            // 0..63 : query row in tile
    const int sub = tid & 3;             // 4 threads per row

    // load Q tile (contiguous source, padded dest rows)
    const float4* Qsrc = (const float4*)(g_Q + (bh*N_ + q0)*HD_);
    for (int i = tid; i < 64*12; i += 256) {
        const int row = i / 12, c = i - row*12;
        *(float4*)&Qs[row*QKV_STRIDE + c*4] = Qsrc[i];
    }

    float o_[12];
    #pragma unroll
    for (int i = 0; i < 12; i++) o_[i] = 0.f;
    float m_i = -1e30f;
    float l_i = 0.f;

    const float* Kbase = g_K + (long long)bh*N_*HD_;
    const float* Vbase = g_V + (long long)bh*N_*HD_;
    const float* Mbase = mask + (long long)(b*N_ + q0)*N_;

    for (int kt = 0; kt < N_/64; kt++) {
        const int k0 = kt*64;
        const float4* Ksrc = (const float4*)(Kbase + k0*HD_);
        const float4* Vsrc = (const float4*)(Vbase + k0*HD_);
        for (int i = tid; i < 64*12; i += 256) {
            const int row = i / 12, c = i - row*12;
            *(float4*)&Ks[row*QKV_STRIDE + c*4] = Ksrc[i];
            *(float4*)&Vs[row*QKV_STRIDE + c*4] = Vsrc[i];
        }
        for (int i = tid; i < 64*16; i += 256) {
            const int row = i >> 4, c = (i & 15) << 2;
            *(float4*)&Ms[row*MP_STRIDE + c] =
                *(const float4*)(Mbase + (long long)row*N_ + k0 + c);
        }
        __syncthreads();

        // S = q . k  (each thread: 16 interleaved j columns)
        float s[16];
        #pragma unroll
        for (int jj = 0; jj < 16; jj++) s[jj] = 0.f;
        #pragma unroll
        for (int c = 0; c < 12; c++) {
            const float4 qv = *(const float4*)&Qs[r*QKV_STRIDE + c*4];
            #pragma unroll
            for (int jj = 0; jj < 16; jj++) {
                const float4 kv = *(const float4*)&Ks[(jj*4 + sub)*QKV_STRIDE + c*4];
                s[jj] += qv.x*kv.x + qv.y*kv.y + qv.z*kv.z + qv.w*kv.w;
            }
        }
        float mx = m_i;
        #pragma unroll
        for (int jj = 0; jj < 16; jj++) {
            s[jj] = s[jj]*SCALE_ + Ms[r*MP_STRIDE + jj*4 + sub];
            mx = fmaxf(mx, s[jj]);
        }
        mx = fmaxf(mx, __shfl_xor_sync(0xffffffffu, mx, 1));
        mx = fmaxf(mx, __shfl_xor_sync(0xffffffffu, mx, 2));
        const float alpha = __expf(m_i - mx);
        m_i = mx;
        l_i *= alpha;
        #pragma unroll
        for (int i = 0; i < 12; i++) o_[i] *= alpha;
        float ps = 0.f;
        #pragma unroll
        for (int jj = 0; jj < 16; jj++) {
            const float p = __expf(s[jj] - mx);
            ps += p;
            Ps[r*MP_STRIDE + jj*4 + sub] = p;
        }
        l_i += ps;
        __syncwarp();   // the 4 writers/readers of row r share a warp

        #pragma unroll 8
        for (int j = 0; j < 64; j++) {
            const float p = Ps[r*MP_STRIDE + j];
            const float4 v0 = *(const float4*)&Vs[j*QKV_STRIDE + sub*12];
            const float4 v1 = *(const float4*)&Vs[j*QKV_STRIDE + sub*12 + 4];
            const float4 v2 = *(const float4*)&Vs[j*QKV_STRIDE + sub*12 + 8];
            o_[0] += p*v0.x;  o_[1] += p*v0.y;  o_[2]  += p*v0.z;  o_[3]  += p*v0.w;
            o_[4] += p*v1.x;  o_[5] += p*v1.y;  o_[6]  += p*v1.z;  o_[7]  += p*v1.w;
            o_[8] += p*v2.x;  o_[9] += p*v2.y;  o_[10] += p*v2.z;  o_[11] += p*v2.w;
        }
        __syncthreads();
    }

    float lt = l_i;
    lt += __shfl_xor_sync(0xffffffffu, lt, 1);
    lt += __shfl_xor_sync(0xffffffffu, lt, 2);
    const float inv = 1.0f / lt;

    float* Orow = g_O + (long long)(b*N_ + q0 + r)*DIM_ + hh*HD_ + sub*12;
    float4 w0 = make_float4(o_[0]*inv, o_[1]*inv, o_[2]*inv, o_[3]*inv);
    float4 w1 = make_float4(o_[4]*inv, o_[5]*inv, o_[6]*inv, o_[7]*inv);
    float4 w2 = make_float4(o_[8]*inv, o_[9]*inv, o_[10]*inv, o_[11]*inv);
    *(float4*)(Orow)     = w0;
    *(float4*)(Orow + 4) = w1;
    *(float4*)(Orow + 8) = w2;
}

// ---------------- launch ------------------------------------------------------
extern "C" void kernel_launch(void* const* d_in, const int* in_sizes, int n_in,
                              void* d_out, int out_size)
{
    const float* x       = (const float*)d_in[0];
    const float* pos     = (const float*)d_in[1];
    const float* mask    = (const float*)d_in[2];
    const int*   npts    = (const int*)d_in[3];   // int32 (jax canonicalized)
    const float* norm1_w = (const float*)d_in[4];
    const float* norm2_w = (const float*)d_in[5];
    const float* w_qkv   = (const float*)d_in[6];
    const float* w_proj  = (const float*)d_in[7];
    const float* b_proj  = (const float*)d_in[8];
    const float* w1      = (const float*)d_in[9];
    const float* w2      = (const float*)d_in[10];
    const float* w3      = (const float*)d_in[11];
    float* out = (float*)d_out;

    float *xa, *O, *h, *hf, *gb;
    cudaGetSymbolAddress((void**)&xa, g_xa);
    cudaGetSymbolAddress((void**)&O,  g_O);
    cudaGetSymbolAddress((void**)&h,  g_h);
    cudaGetSymbolAddress((void**)&hf, g_hf);
    cudaGetSymbolAddress((void**)&gb, g_gb);

    cudaFuncSetAttribute(attn_kernel,
                         cudaFuncAttributeMaxDynamicSharedMemorySize,
                         ATTN_SMEM_BYTES);

    // 1) xa = rmsnorm(x) * norm1_w
    rmsnorm_kernel<<<M_, 128>>>(x, norm1_w, xa);

    // 2) qkv GEMM + pos add + split into Q/K/V [B,H,N,HD]
    gemm_kernel<DIM_, MODE_QKV><<<dim3(3*DIM_/128, M_/128), 256>>>(
        xa, w_qkv, nullptr, pos, nullptr, nullptr);

    // 3) attention -> g_O [B,N,H*HD]
    attn_kernel<<<dim3(N_/64, B_*H_), 256, ATTN_SMEM_BYTES>>>(mask);

    // 4) h = x + O @ w_proj^T + b_proj
    gemm_kernel<DIM_, MODE_PROJ><<<dim3(DIM_/128, M_/128), 256>>>(
        O, w_proj, h, b_proj, x, nullptr);

    // 5) hf = rmsnorm(h) * norm2_w
    rmsnorm_kernel<<<M_, 128>>>(h, norm2_w, hf);

    // 6) g = silu(hf @ w1^T)
    gemm_kernel<DIM_, MODE_SILU><<<dim3(HID_/128, M_/128), 256>>>(
        hf, w1, gb, nullptr, nullptr, nullptr);

    // 7) g *= hf @ w3^T
    gemm_kernel<DIM_, MODE_MUL><<<dim3(HID_/128, M_/128), 256>>>(
        hf, w3, gb, nullptr, nullptr, nullptr);

    // 8) out = keep ? h + g @ w2^T : 0
    gemm_kernel<HID_, MODE_FINAL><<<dim3(DIM_/128, M_/128), 256>>>(
        gb, w2, out, nullptr, h, npts);
}

// round 3
// speedup vs baseline: 1.2197x; 1.2197x over previous
#include <cuda_runtime.h>
#include <cstdint>

#define B_    4
#define N_    2048
#define DIM_  384
#define H_    8
#define HD_   48
#define HID_  1024
#define M_    (B_*N_)          // 8192
#define SCALE_ 0.14433756729740643f   // 48^-0.5
#define EPS_   1e-5f

// ---------------- scratch (no allocation allowed; __device__ globals) ----------
__device__ float g_xa [M_*DIM_];
__device__ float g_Q  [M_*DIM_];   // [B,H,N,HD]
__device__ float g_K  [M_*DIM_];
__device__ float g_V  [M_*DIM_];
__device__ float g_O  [M_*DIM_];   // [B,N,H*HD]
__device__ float g_h  [M_*DIM_];
__device__ float g_hf [M_*DIM_];
__device__ float g_gb [M_*HID_];

// ---------------- RMSNorm: one row (384) per block of 128 threads --------------
__global__ void rmsnorm_kernel(const float* __restrict__ src,
                               const float* __restrict__ w,
                               float* __restrict__ dst) {
    const int row = blockIdx.x;
    const int tid = threadIdx.x;
    const float* xr = src + row*DIM_;
    float v0 = xr[tid], v1 = xr[tid+128], v2 = xr[tid+256];
    float s = v0*v0 + v1*v1 + v2*v2;
    #pragma unroll
    for (int o = 16; o > 0; o >>= 1) s += __shfl_xor_sync(0xffffffffu, s, o);
    __shared__ float red[4];
    if ((tid & 31) == 0) red[tid >> 5] = s;
    __syncthreads();
    float tot = red[0] + red[1] + red[2] + red[3];
    float sc = rsqrtf(tot * (1.0f/DIM_) + EPS_);
    float* dr = dst + row*DIM_;
    dr[tid]     = v0*sc*w[tid];
    dr[tid+128] = v1*sc*w[tid+128];
    dr[tid+256] = v2*sc*w[tid+256];
}

// ---------------- tf32 tensor-core GEMM: C = A[M,K] * W[N,K]^T -----------------
// 128x128 block tile, BK=16, 256 threads = 8 warps (2M x 4N), warp tile 64x32,
// mma.sync.m16n8k8.tf32. Epilogue selected by MODE.
#define MODE_QKV   1
#define MODE_PROJ  2
#define MODE_SILU  3
#define MODE_MUL   4
#define MODE_FINAL 5

__device__ __forceinline__ uint32_t f2tf32(float f) {
    uint32_t u;
    asm("cvt.rna.tf32.f32 %0, %1;" : "=r"(u) : "f"(f));
    return u;
}

template<int KDIM, int MODE>
__global__ void __launch_bounds__(256, 2) gemm_tc_kernel(
    const float* __restrict__ A, const float* __restrict__ W,
    float* __restrict__ C,
    const float* __restrict__ aux1,   // pos | b_proj | - | - | -
    const float* __restrict__ aux2,   // -   | x      | - | - | h
    const int* __restrict__ npts)
{
    __shared__ uint32_t As[16][136];   // [k][m], tf32 bits; pad 136 -> frag loads conflict-free
    __shared__ uint32_t Bs[16][136];   // [k][n]

    const int tid  = threadIdx.x;
    const int bm   = blockIdx.y << 7;
    const int bn   = blockIdx.x << 7;
    const int warp = tid >> 5;
    const int wm   = (warp >> 2) * 64;     // warp M offset within block
    const int wn   = (warp & 3) * 32;      // warp N offset within block
    const int lane = tid & 31;
    const int gid  = lane >> 2;            // 0..7
    const int tg   = lane & 3;             // 0..3
    const int lr   = tid >> 2;             // 0..63 (global load row)
    const int lc   = (tid & 3) << 2;       // 0,4,8,12 (global load col)

    float acc[4][4][4];
    #pragma unroll
    for (int mt = 0; mt < 4; mt++)
        #pragma unroll
        for (int nt = 0; nt < 4; nt++)
            #pragma unroll
            for (int e = 0; e < 4; e++) acc[mt][nt][e] = 0.f;

    const float* Ap = A + (long long)(bm + lr)*KDIM + lc;
    const float* Wp = W + (long long)(bn + lr)*KDIM + lc;

    for (int k0 = 0; k0 < KDIM; k0 += 16) {
        float4 a0 = *(const float4*)(Ap + k0);
        float4 a1 = *(const float4*)(Ap + (long long)64*KDIM + k0);
        float4 b0 = *(const float4*)(Wp + k0);
        float4 b1 = *(const float4*)(Wp + (long long)64*KDIM + k0);
        __syncthreads();
        As[lc+0][lr]    = f2tf32(a0.x); As[lc+1][lr]    = f2tf32(a0.y);
        As[lc+2][lr]    = f2tf32(a0.z); As[lc+3][lr]    = f2tf32(a0.w);
        As[lc+0][lr+64] = f2tf32(a1.x); As[lc+1][lr+64] = f2tf32(a1.y);
        As[lc+2][lr+64] = f2tf32(a1.z); As[lc+3][lr+64] = f2tf32(a1.w);
        Bs[lc+0][lr]    = f2tf32(b0.x); Bs[lc+1][lr]    = f2tf32(b0.y);
        Bs[lc+2][lr]    = f2tf32(b0.z); Bs[lc+3][lr]    = f2tf32(b0.w);
        Bs[lc+0][lr+64] = f2tf32(b1.x); Bs[lc+1][lr+64] = f2tf32(b1.y);
        Bs[lc+2][lr+64] = f2tf32(b1.z); Bs[lc+3][lr+64] = f2tf32(b1.w);
        __syncthreads();

        #pragma unroll
        for (int ks = 0; ks < 2; ks++) {
            const int kb = ks << 3;
            uint32_t af[4][4];
            uint32_t bf[4][2];
            #pragma unroll
            for (int mt = 0; mt < 4; mt++) {
                const int m0 = wm + mt*16;
                af[mt][0] = As[kb+tg  ][m0+gid];
                af[mt][1] = As[kb+tg  ][m0+gid+8];
                af[mt][2] = As[kb+tg+4][m0+gid];
                af[mt][3] = As[kb+tg+4][m0+gid+8];
            }
            #pragma unroll
            for (int nt = 0; nt < 4; nt++) {
                const int n0 = wn + nt*8;
                bf[nt][0] = Bs[kb+tg  ][n0+gid];
                bf[nt][1] = Bs[kb+tg+4][n0+gid];
            }
            #pragma unroll
            for (int mt = 0; mt < 4; mt++)
                #pragma unroll
                for (int nt = 0; nt < 4; nt++) {
                    asm volatile(
                        "mma.sync.aligned.m16n8k8.row.col.f32.tf32.tf32.f32 "
                        "{%0,%1,%2,%3}, {%4,%5,%6,%7}, {%8,%9}, {%0,%1,%2,%3};"
                        : "+f"(acc[mt][nt][0]), "+f"(acc[mt][nt][1]),
                          "+f"(acc[mt][nt][2]), "+f"(acc[mt][nt][3])
                        : "r"(af[mt][0]), "r"(af[mt][1]),
                          "r"(af[mt][2]), "r"(af[mt][3]),
                          "r"(bf[nt][0]), "r"(bf[nt][1]));
                }
        }
    }

    // epilogue: c0:(gid, tg*2) c1:(gid, tg*2+1) c2:(gid+8, tg*2) c3:(gid+8, tg*2+1)
    #pragma unroll
    for (int mt = 0; mt < 4; mt++) {
        #pragma unroll
        for (int nt = 0; nt < 4; nt++) {
            #pragma unroll
            for (int e = 0; e < 4; e++) {
                const int m = bm + wm + mt*16 + gid + ((e & 2) ? 8 : 0);
                const int n = bn + wn + nt*8 + tg*2 + (e & 1);
                float v = acc[mt][nt][e];
                if constexpr (MODE == MODE_QKV) {
                    const int b    = m >> 11;
                    const int ns   = m & 2047;
                    const int part = n / DIM_;
                    const int rem  = n - part*DIM_;
                    const int hh   = rem / HD_;
                    const int hd   = rem - hh*HD_;
                    if (part < 2) v += aux1[(b*N_ + ns)*HD_ + hd];
                    float* dst = (part == 0) ? g_Q : (part == 1 ? g_K : g_V);
                    dst[(((b << 3) + hh)*N_ + ns)*HD_ + hd] = v;
                } else if constexpr (MODE == MODE_PROJ) {
                    C[m*DIM_ + n] = v + aux1[n] + aux2[m*DIM_ + n];
                } else if constexpr (MODE == MODE_SILU) {
                    C[m*HID_ + n] = v / (1.0f + __expf(-v));
                } else if constexpr (MODE == MODE_MUL) {
                    C[m*HID_ + n] *= v;
                } else if constexpr (MODE == MODE_FINAL) {
                    const int np = npts[m >> 11];
                    C[m*DIM_ + n] = ((m & 2047) < np)
                                    ? (aux2[m*DIM_ + n] + v) : 0.0f;
                }
            }
        }
    }
}

// ---------------- flash attention: block = (bh, 64-row q tile) -----------------
// smem: Qs/Ks/Vs [64][52] (padded), Ms/Ps [64][68] (padded). online softmax.
#define QKV_STRIDE 52
#define MP_STRIDE  68
#define ATTN_SMEM_BYTES ((3*64*QKV_STRIDE + 2*64*MP_STRIDE) * 4)

__global__ void __launch_bounds__(256, 2) attn_kernel(const float* __restrict__ mask) {
    extern __shared__ float sm[];
    float* Qs = sm;
    float* Ks = sm + 64*QKV_STRIDE;
    float* Vs = sm + 2*64*QKV_STRIDE;
    float* Ms = sm + 3*64*QKV_STRIDE;
    float* Ps = Ms + 64*MP_STRIDE;

    const int bh  = blockIdx.y;          // b*8 + h
    const int b   = bh >> 3;
    const int hh  = bh & 7;
    const int q0  = blockIdx.x * 64;
    const int tid = threadIdx.x;
    const int r   = tid >> 2;            // 0..63 : query row in tile
    const int sub = tid & 3;             // 4 threads per row

    // load Q tile (contiguous source, padded dest rows)
    const float4* Qsrc = (const float4*)(g_Q + (bh*N_ + q0)*HD_);
    for (int i = tid; i < 64*12; i += 256) {
        const int row = i / 12, c = i - row*12;
        *(float4*)&Qs[row*QKV_STRIDE + c*4] = Qsrc[i];
    }

    float o_[12];
    #pragma unroll
    for (int i = 0; i < 12; i++) o_[i] = 0.f;
    float m_i = -1e30f;
    float l_i = 0.f;

    const float* Kbase = g_K + (long long)bh*N_*HD_;
    const float* Vbase = g_V + (long long)bh*N_*HD_;
    const float* Mbase = mask + (long long)(b*N_ + q0)*N_;

    for (int kt = 0; kt < N_/64; kt++) {
        const int k0 = kt*64;
        const float4* Ksrc = (const float4*)(Kbase + k0*HD_);
        const float4* Vsrc = (const float4*)(Vbase + k0*HD_);
        for (int i = tid; i < 64*12; i += 256) {
            const int row = i / 12, c = i - row*12;
            *(float4*)&Ks[row*QKV_STRIDE + c*4] = Ksrc[i];
            *(float4*)&Vs[row*QKV_STRIDE + c*4] = Vsrc[i];
        }
        for (int i = tid; i < 64*16; i += 256) {
            const int row = i >> 4, c = (i & 15) << 2;
            *(float4*)&Ms[row*MP_STRIDE + c] =
                *(const float4*)(Mbase + (long long)row*N_ + k0 + c);
        }
        __syncthreads();

        // S = q . k  (each thread: 16 interleaved j columns)
        float s[16];
        #pragma unroll
        for (int jj = 0; jj < 16; jj++) s[jj] = 0.f;
        #pragma unroll
        for (int c = 0; c < 12; c++) {
            const float4 qv = *(const float4*)&Qs[r*QKV_STRIDE + c*4];
            #pragma unroll
            for (int jj = 0; jj < 16; jj++) {
                const float4 kv = *(const float4*)&Ks[(jj*4 + sub)*QKV_STRIDE + c*4];
                s[jj] += qv.x*kv.x + qv.y*kv.y + qv.z*kv.z + qv.w*kv.w;
            }
        }
        float mx = m_i;
        #pragma unroll
        for (int jj = 0; jj < 16; jj++) {
            s[jj] = s[jj]*SCALE_ + Ms[r*MP_STRIDE + jj*4 + sub];
            mx = fmaxf(mx, s[jj]);
        }
        mx = fmaxf(mx, __shfl_xor_sync(0xffffffffu, mx, 1));
        mx = fmaxf(mx, __shfl_xor_sync(0xffffffffu, mx, 2));
        const float alpha = __expf(m_i - mx);
        m_i = mx;
        l_i *= alpha;
        #pragma unroll
        for (int i = 0; i < 12; i++) o_[i] *= alpha;
        float ps = 0.f;
        #pragma unroll
        for (int jj = 0; jj < 16; jj++) {
            const float p = __expf(s[jj] - mx);
            ps += p;
            Ps[r*MP_STRIDE + jj*4 + sub] = p;
        }
        l_i += ps;
        __syncwarp();   // the 4 writers/readers of row r share a warp

        #pragma unroll 8
        for (int j = 0; j < 64; j++) {
            const float p = Ps[r*MP_STRIDE + j];
            const float4 v0 = *(const float4*)&Vs[j*QKV_STRIDE + sub*12];
            const float4 v1 = *(const float4*)&Vs[j*QKV_STRIDE + sub*12 + 4];
            const float4 v2 = *(const float4*)&Vs[j*QKV_STRIDE + sub*12 + 8];
            o_[0] += p*v0.x;  o_[1] += p*v0.y;  o_[2]  += p*v0.z;  o_[3]  += p*v0.w;
            o_[4] += p*v1.x;  o_[5] += p*v1.y;  o_[6]  += p*v1.z;  o_[7]  += p*v1.w;
            o_[8] += p*v2.x;  o_[9] += p*v2.y;  o_[10] += p*v2.z;  o_[11] += p*v2.w;
        }
        __syncthreads();
    }

    float lt = l_i;
    lt += __shfl_xor_sync(0xffffffffu, lt, 1);
    lt += __shfl_xor_sync(0xffffffffu, lt, 2);
    const float inv = 1.0f / lt;

    float* Orow = g_O + (long long)(b*N_ + q0 + r)*DIM_ + hh*HD_ + sub*12;
    float4 w0 = make_float4(o_[0]*inv, o_[1]*inv, o_[2]*inv, o_[3]*inv);
    float4 w1 = make_float4(o_[4]*inv, o_[5]*inv, o_[6]*inv, o_[7]*inv);
    float4 w2 = make_float4(o_[8]*inv, o_[9]*inv, o_[10]*inv, o_[11]*inv);
    *(float4*)(Orow)     = w0;
    *(float4*)(Orow + 4) = w1;
    *(float4*)(Orow + 8) = w2;
}

// ---------------- launch ------------------------------------------------------
extern "C" void kernel_launch(void* const* d_in, const int* in_sizes, int n_in,
                              void* d_out, int out_size)
{
    const float* x       = (const float*)d_in[0];
    const float* pos     = (const float*)d_in[1];
    const float* mask    = (const float*)d_in[2];
    const int*   npts    = (const int*)d_in[3];   // int32 (jax canonicalized)
    const float* norm1_w = (const float*)d_in[4];
    const float* norm2_w = (const float*)d_in[5];
    const float* w_qkv   = (const float*)d_in[6];
    const float* w_proj  = (const float*)d_in[7];
    const float* b_proj  = (const float*)d_in[8];
    const float* w1      = (const float*)d_in[9];
    const float* w2      = (const float*)d_in[10];
    const float* w3      = (const float*)d_in[11];
    float* out = (float*)d_out;

    float *xa, *O, *h, *hf, *gb;
    cudaGetSymbolAddress((void**)&xa, g_xa);
    cudaGetSymbolAddress((void**)&O,  g_O);
    cudaGetSymbolAddress((void**)&h,  g_h);
    cudaGetSymbolAddress((void**)&hf, g_hf);
    cudaGetSymbolAddress((void**)&gb, g_gb);

    cudaFuncSetAttribute(attn_kernel,
                         cudaFuncAttributeMaxDynamicSharedMemorySize,
                         ATTN_SMEM_BYTES);

    // 1) xa = rmsnorm(x) * norm1_w
    rmsnorm_kernel<<<M_, 128>>>(x, norm1_w, xa);

    // 2) qkv GEMM + pos add + split into Q/K/V [B,H,N,HD]
    gemm_tc_kernel<DIM_, MODE_QKV><<<dim3(3*DIM_/128, M_/128), 256>>>(
        xa, w_qkv, nullptr, pos, nullptr, nullptr);

    // 3) attention -> g_O [B,N,H*HD]
    attn_kernel<<<dim3(N_/64, B_*H_), 256, ATTN_SMEM_BYTES>>>(mask);

    // 4) h = x + O @ w_proj^T + b_proj
    gemm_tc_kernel<DIM_, MODE_PROJ><<<dim3(DIM_/128, M_/128), 256>>>(
        O, w_proj, h, b_proj, x, nullptr);

    // 5) hf = rmsnorm(h) * norm2_w
    rmsnorm_kernel<<<M_, 128>>>(h, norm2_w, hf);

    // 6) g = silu(hf @ w1^T)
    gemm_tc_kernel<DIM_, MODE_SILU><<<dim3(HID_/128, M_/128), 256>>>(
        hf, w1, gb, nullptr, nullptr, nullptr);

    // 7) g *= hf @ w3^T
    gemm_tc_kernel<DIM_, MODE_MUL><<<dim3(HID_/128, M_/128), 256>>>(
        hf, w3, gb, nullptr, nullptr, nullptr);

    // 8) out = keep ? h + g @ w2^T : 0
    gemm_tc_kernel<HID_, MODE_FINAL><<<dim3(DIM_/128, M_/128), 256>>>(
        gb, w2, out, nullptr, h, npts);
}

// round 4
// speedup vs baseline: 2.6625x; 2.1828x over previous
#include <cuda_runtime.h>
#include <cstdint>

#define B_    4
#define N_    2048
#define DIM_  384
#define H_    8
#define HD_   48
#define HID_  1024
#define M_    (B_*N_)          // 8192
#define SCALE_ 0.14433756729740643f   // 48^-0.5
#define EPS_   1e-5f

// ---------------- scratch (no allocation allowed; __device__ globals) ----------
__device__ float g_xa [M_*DIM_];
__device__ float g_Q  [M_*DIM_];   // [B,H,N,HD]
__device__ float g_K  [M_*DIM_];
__device__ float g_V  [M_*DIM_];
__device__ float g_O  [M_*DIM_];   // [B,N,H*HD]
__device__ float g_h  [M_*DIM_];
__device__ float g_hf [M_*DIM_];
__device__ float g_gb [M_*HID_];

__device__ __forceinline__ uint32_t f2tf32(float f) {
    uint32_t u;
    asm("cvt.rna.tf32.f32 %0, %1;" : "=r"(u) : "f"(f));
    return u;
}

__device__ __forceinline__ void mma_tf32(float c[4], const uint32_t a[4], const uint32_t b[2]) {
    asm volatile(
        "mma.sync.aligned.m16n8k8.row.col.f32.tf32.tf32.f32 "
        "{%0,%1,%2,%3}, {%4,%5,%6,%7}, {%8,%9}, {%0,%1,%2,%3};"
        : "+f"(c[0]), "+f"(c[1]), "+f"(c[2]), "+f"(c[3])
        : "r"(a[0]), "r"(a[1]), "r"(a[2]), "r"(a[3]),
          "r"(b[0]), "r"(b[1]));
}

// ---------------- RMSNorm: one row (384) per block of 128 threads --------------
__global__ void rmsnorm_kernel(const float* __restrict__ src,
                               const float* __restrict__ w,
                               float* __restrict__ dst) {
    const int row = blockIdx.x;
    const int tid = threadIdx.x;
    const float* xr = src + row*DIM_;
    float v0 = xr[tid], v1 = xr[tid+128], v2 = xr[tid+256];
    float s = v0*v0 + v1*v1 + v2*v2;
    #pragma unroll
    for (int o = 16; o > 0; o >>= 1) s += __shfl_xor_sync(0xffffffffu, s, o);
    __shared__ float red[4];
    if ((tid & 31) == 0) red[tid >> 5] = s;
    __syncthreads();
    float tot = red[0] + red[1] + red[2] + red[3];
    float sc = rsqrtf(tot * (1.0f/DIM_) + EPS_);
    float* dr = dst + row*DIM_;
    dr[tid]     = v0*sc*w[tid];
    dr[tid+128] = v1*sc*w[tid+128];
    dr[tid+256] = v2*sc*w[tid+256];
}

// ---------------- tf32 tensor-core GEMM: C = A[M,K] * W[N,K]^T -----------------
#define MODE_QKV   1
#define MODE_PROJ  2
#define MODE_SILU  3
#define MODE_MUL   4
#define MODE_FINAL 5

template<int KDIM, int MODE>
__global__ void __launch_bounds__(256, 2) gemm_tc_kernel(
    const float* __restrict__ A, const float* __restrict__ W,
    float* __restrict__ C,
    const float* __restrict__ aux1,   // pos | b_proj | - | - | -
    const float* __restrict__ aux2,   // -   | x      | - | - | h
    const int* __restrict__ npts)
{
    __shared__ uint32_t As[16][136];
    __shared__ uint32_t Bs[16][136];

    const int tid  = threadIdx.x;
    const int bm   = blockIdx.y << 7;
    const int bn   = blockIdx.x << 7;
    const int warp = tid >> 5;
    const int wm   = (warp >> 2) * 64;
    const int wn   = (warp & 3) * 32;
    const int lane = tid & 31;
    const int gid  = lane >> 2;
    const int tg   = lane & 3;
    const int lr   = tid >> 2;
    const int lc   = (tid & 3) << 2;

    float acc[4][4][4];
    #pragma unroll
    for (int mt = 0; mt < 4; mt++)
        #pragma unroll
        for (int nt = 0; nt < 4; nt++)
            #pragma unroll
            for (int e = 0; e < 4; e++) acc[mt][nt][e] = 0.f;

    const float* Ap = A + (long long)(bm + lr)*KDIM + lc;
    const float* Wp = W + (long long)(bn + lr)*KDIM + lc;

    for (int k0 = 0; k0 < KDIM; k0 += 16) {
        float4 a0 = *(const float4*)(Ap + k0);
        float4 a1 = *(const float4*)(Ap + (long long)64*KDIM + k0);
        float4 b0 = *(const float4*)(Wp + k0);
        float4 b1 = *(const float4*)(Wp + (long long)64*KDIM + k0);
        __syncthreads();
        As[lc+0][lr]    = f2tf32(a0.x); As[lc+1][lr]    = f2tf32(a0.y);
        As[lc+2][lr]    = f2tf32(a0.z); As[lc+3][lr]    = f2tf32(a0.w);
        As[lc+0][lr+64] = f2tf32(a1.x); As[lc+1][lr+64] = f2tf32(a1.y);
        As[lc+2][lr+64] = f2tf32(a1.z); As[lc+3][lr+64] = f2tf32(a1.w);
        Bs[lc+0][lr]    = f2tf32(b0.x); Bs[lc+1][lr]    = f2tf32(b0.y);
        Bs[lc+2][lr]    = f2tf32(b0.z); Bs[lc+3][lr]    = f2tf32(b0.w);
        Bs[lc+0][lr+64] = f2tf32(b1.x); Bs[lc+1][lr+64] = f2tf32(b1.y);
        Bs[lc+2][lr+64] = f2tf32(b1.z); Bs[lc+3][lr+64] = f2tf32(b1.w);
        __syncthreads();

        #pragma unroll
        for (int ks = 0; ks < 2; ks++) {
            const int kb = ks << 3;
            uint32_t af[4][4];
            uint32_t bf[4][2];
            #pragma unroll
            for (int mt = 0; mt < 4; mt++) {
                const int m0 = wm + mt*16;
                af[mt][0] = As[kb+tg  ][m0+gid];
                af[mt][1] = As[kb+tg  ][m0+gid+8];
                af[mt][2] = As[kb+tg+4][m0+gid];
                af[mt][3] = As[kb+tg+4][m0+gid+8];
            }
            #pragma unroll
            for (int nt = 0; nt < 4; nt++) {
                const int n0 = wn + nt*8;
                bf[nt][0] = Bs[kb+tg  ][n0+gid];
                bf[nt][1] = Bs[kb+tg+4][n0+gid];
            }
            #pragma unroll
            for (int mt = 0; mt < 4; mt++)
                #pragma unroll
                for (int nt = 0; nt < 4; nt++)
                    mma_tf32(acc[mt][nt], af[mt], bf[nt]);
        }
    }

    #pragma unroll
    for (int mt = 0; mt < 4; mt++) {
        #pragma unroll
        for (int nt = 0; nt < 4; nt++) {
            #pragma unroll
            for (int e = 0; e < 4; e++) {
                const int m = bm + wm + mt*16 + gid + ((e & 2) ? 8 : 0);
                const int n = bn + wn + nt*8 + tg*2 + (e & 1);
                float v = acc[mt][nt][e];
                if constexpr (MODE == MODE_QKV) {
                    const int b    = m >> 11;
                    const int ns   = m & 2047;
                    const int part = n / DIM_;
                    const int rem  = n - part*DIM_;
                    const int hh   = rem / HD_;
                    const int hd   = rem - hh*HD_;
                    if (part < 2) v += aux1[(b*N_ + ns)*HD_ + hd];
                    float* dst = (part == 0) ? g_Q : (part == 1 ? g_K : g_V);
                    dst[(((b << 3) + hh)*N_ + ns)*HD_ + hd] = v;
                } else if constexpr (MODE == MODE_PROJ) {
                    C[m*DIM_ + n] = v + aux1[n] + aux2[m*DIM_ + n];
                } else if constexpr (MODE == MODE_SILU) {
                    C[m*HID_ + n] = v / (1.0f + __expf(-v));
                } else if constexpr (MODE == MODE_MUL) {
                    C[m*HID_ + n] *= v;
                } else if constexpr (MODE == MODE_FINAL) {
                    const int np = npts[m >> 11];
                    C[m*DIM_ + n] = ((m & 2047) < np)
                                    ? (aux2[m*DIM_ + n] + v) : 0.0f;
                }
            }
        }
    }
}

// ---------------- tensor-core flash attention ----------------------------------
// block = 128 thr (4 warps), q-tile 64 (warp => m16 slab), k-tile 64, HD=48.
// smem words: KQ [64][52] (Q then K, tf32) | Vt [48][68] (tf32, transposed)
//           | Ms [64][68] (f32 mask) | Ps [64][68] (tf32 P)
#define AT_KQ_W   (64*52)
#define AT_VT_W   (48*68)
#define AT_MS_W   (64*68)
#define AT_PS_W   (64*68)
#define AT_SMEM_BYTES ((AT_KQ_W + AT_VT_W + AT_MS_W + AT_PS_W) * 4)

__global__ void __launch_bounds__(128) attn_tc_kernel(const float* __restrict__ mask) {
    extern __shared__ uint32_t smw[];
    uint32_t* Ks = smw;                              // [64][52] (Q first, then K)
    uint32_t* Vt = smw + AT_KQ_W;                    // [48][68]
    float*    Ms = (float*)(smw + AT_KQ_W + AT_VT_W);// [64][68]
    uint32_t* Ps = smw + AT_KQ_W + AT_VT_W + AT_MS_W;// [64][68]

    const int bh  = blockIdx.y;
    const int b   = bh >> 3;
    const int hh  = bh & 7;
    const int q0  = blockIdx.x * 64;
    const int tid = threadIdx.x;
    const int warp = tid >> 5;
    const int lane = tid & 31;
    const int gid  = lane >> 2;
    const int tg   = lane & 3;
    const int m0   = warp * 16;

    // ---- stage Q tile (tf32) and pull Q fragments into registers ----
    const float4* Qsrc = (const float4*)(g_Q + ((long long)bh*N_ + q0)*HD_);
    for (int i = tid; i < 64*12; i += 128) {
        const int row = i / 12, c = i - row*12;
        float4 v = Qsrc[i];
        uint32_t* p = &Ks[row*52 + c*4];
        p[0] = f2tf32(v.x); p[1] = f2tf32(v.y);
        p[2] = f2tf32(v.z); p[3] = f2tf32(v.w);
    }
    __syncthreads();
    uint32_t qf[6][4];
    #pragma unroll
    for (int ks = 0; ks < 6; ks++) {
        const int kb = ks*8;
        qf[ks][0] = Ks[(m0+gid  )*52 + kb+tg];
        qf[ks][1] = Ks[(m0+gid+8)*52 + kb+tg];
        qf[ks][2] = Ks[(m0+gid  )*52 + kb+tg+4];
        qf[ks][3] = Ks[(m0+gid+8)*52 + kb+tg+4];
    }
    __syncthreads();

    float oacc[6][4];
    #pragma unroll
    for (int nt = 0; nt < 6; nt++)
        #pragma unroll
        for (int e = 0; e < 4; e++) oacc[nt][e] = 0.f;
    float mr0 = -1e30f, mr1 = -1e30f, lr0 = 0.f, lr1 = 0.f;

    const float* Kbase = g_K + (long long)bh*N_*HD_;
    const float* Vbase = g_V + (long long)bh*N_*HD_;
    const float* Mbase = mask + ((long long)b*N_ + q0)*N_;

    for (int kt = 0; kt < N_/64; kt++) {
        const int k0 = kt*64;
        const float4* Ksrc = (const float4*)(Kbase + k0*HD_);
        const float4* Vsrc = (const float4*)(Vbase + k0*HD_);
        for (int i = tid; i < 64*12; i += 128) {
            const int row = i / 12, c = i - row*12;
            float4 kv = Ksrc[i];
            uint32_t* p = &Ks[row*52 + c*4];
            p[0] = f2tf32(kv.x); p[1] = f2tf32(kv.y);
            p[2] = f2tf32(kv.z); p[3] = f2tf32(kv.w);
            float4 vv = Vsrc[i];
            Vt[(c*4+0)*68 + row] = f2tf32(vv.x);
            Vt[(c*4+1)*68 + row] = f2tf32(vv.y);
            Vt[(c*4+2)*68 + row] = f2tf32(vv.z);
            Vt[(c*4+3)*68 + row] = f2tf32(vv.w);
        }
        for (int i = tid; i < 64*16; i += 128) {
            const int row = i >> 4, c = (i & 15) << 2;
            *(float4*)&Ms[row*68 + c] =
                *(const float4*)(Mbase + (long long)row*N_ + k0 + c);
        }
        __syncthreads();

        // ---- S = Q . K^T ----
        float sacc[8][4];
        #pragma unroll
        for (int nt = 0; nt < 8; nt++)
            #pragma unroll
            for (int e = 0; e < 4; e++) sacc[nt][e] = 0.f;
        #pragma unroll
        for (int ks = 0; ks < 6; ks++) {
            const int kb = ks*8;
            uint32_t bf[8][2];
            #pragma unroll
            for (int nt = 0; nt < 8; nt++) {
                bf[nt][0] = Ks[(nt*8+gid)*52 + kb+tg];
                bf[nt][1] = Ks[(nt*8+gid)*52 + kb+tg+4];
            }
            #pragma unroll
            for (int nt = 0; nt < 8; nt++)
                mma_tf32(sacc[nt], qf[ks], bf[nt]);
        }

        // ---- online softmax (rows gid / gid+8 of this warp's m16 slab) ----
        float mx0 = mr0, mx1 = mr1;
        #pragma unroll
        for (int nt = 0; nt < 8; nt++) {
            const int col = nt*8 + tg*2;
            float v0 = sacc[nt][0]*SCALE_ + Ms[(m0+gid  )*68 + col];
            float v1 = sacc[nt][1]*SCALE_ + Ms[(m0+gid  )*68 + col+1];
            float v2 = sacc[nt][2]*SCALE_ + Ms[(m0+gid+8)*68 + col];
            float v3 = sacc[nt][3]*SCALE_ + Ms[(m0+gid+8)*68 + col+1];
            sacc[nt][0] = v0; sacc[nt][1] = v1; sacc[nt][2] = v2; sacc[nt][3] = v3;
            mx0 = fmaxf(mx0, fmaxf(v0, v1));
            mx1 = fmaxf(mx1, fmaxf(v2, v3));
        }
        mx0 = fmaxf(mx0, __shfl_xor_sync(0xffffffffu, mx0, 1));
        mx0 = fmaxf(mx0, __shfl_xor_sync(0xffffffffu, mx0, 2));
        mx1 = fmaxf(mx1, __shfl_xor_sync(0xffffffffu, mx1, 1));
        mx1 = fmaxf(mx1, __shfl_xor_sync(0xffffffffu, mx1, 2));
        const float a0 = __expf(mr0 - mx0);
        const float a1 = __expf(mr1 - mx1);
        mr0 = mx0; mr1 = mx1;
        lr0 *= a0;  lr1 *= a1;
        #pragma unroll
        for (int nt = 0; nt < 6; nt++) {
            oacc[nt][0] *= a0; oacc[nt][1] *= a0;
            oacc[nt][2] *= a1; oacc[nt][3] *= a1;
        }
        float ps0 = 0.f, ps1 = 0.f;
        #pragma unroll
        for (int nt = 0; nt < 8; nt++) {
            const int col = nt*8 + tg*2;
            float p0 = __expf(sacc[nt][0] - mx0);
            float p1 = __expf(sacc[nt][1] - mx0);
            float p2 = __expf(sacc[nt][2] - mx1);
            float p3 = __expf(sacc[nt][3] - mx1);
            ps0 += p0 + p1;
            ps1 += p2 + p3;
            Ps[(m0+gid  )*68 + col  ] = f2tf32(p0);
            Ps[(m0+gid  )*68 + col+1] = f2tf32(p1);
            Ps[(m0+gid+8)*68 + col  ] = f2tf32(p2);
            Ps[(m0+gid+8)*68 + col+1] = f2tf32(p3);
        }
        lr0 += ps0; lr1 += ps1;
        __syncwarp();

        // ---- O += P . V ----
        #pragma unroll
        for (int ks = 0; ks < 8; ks++) {
            const int kb = ks*8;
            uint32_t af[4];
            af[0] = Ps[(m0+gid  )*68 + kb+tg];
            af[1] = Ps[(m0+gid+8)*68 + kb+tg];
            af[2] = Ps[(m0+gid  )*68 + kb+tg+4];
            af[3] = Ps[(m0+gid+8)*68 + kb+tg+4];
            #pragma unroll
            for (int nt = 0; nt < 6; nt++) {
                uint32_t bv[2];
                bv[0] = Vt[(nt*8+gid)*68 + kb+tg];
                bv[1] = Vt[(nt*8+gid)*68 + kb+tg+4];
                mma_tf32(oacc[nt], af, bv);
            }
        }
        __syncthreads();
    }

    lr0 += __shfl_xor_sync(0xffffffffu, lr0, 1);
    lr0 += __shfl_xor_sync(0xffffffffu, lr0, 2);
    lr1 += __shfl_xor_sync(0xffffffffu, lr1, 1);
    lr1 += __shfl_xor_sync(0xffffffffu, lr1, 2);
    const float i0 = 1.0f / lr0;
    const float i1 = 1.0f / lr1;

    const long long r0 = (long long)(b*N_ + q0 + m0 + gid)*DIM_ + hh*HD_;
    const long long r1 = r0 + 8LL*DIM_;
    #pragma unroll
    for (int nt = 0; nt < 6; nt++) {
        const int col = nt*8 + tg*2;
        *(float2*)&g_O[r0 + col] = make_float2(oacc[nt][0]*i0, oacc[nt][1]*i0);
        *(float2*)&g_O[r1 + col] = make_float2(oacc[nt][2]*i1, oacc[nt][3]*i1);
    }
}

// ---------------- launch ------------------------------------------------------
extern "C" void kernel_launch(void* const* d_in, const int* in_sizes, int n_in,
                              void* d_out, int out_size)
{
    const float* x       = (const float*)d_in[0];
    const float* pos     = (const float*)d_in[1];
    const float* mask    = (const float*)d_in[2];
    const int*   npts    = (const int*)d_in[3];   // int32 (jax canonicalized)
    const float* norm1_w = (const float*)d_in[4];
    const float* norm2_w = (const float*)d_in[5];
    const float* w_qkv   = (const float*)d_in[6];
    const float* w_proj  = (const float*)d_in[7];
    const float* b_proj  = (const float*)d_in[8];
    const float* w1      = (const float*)d_in[9];
    const float* w2      = (const float*)d_in[10];
    const float* w3      = (const float*)d_in[11];
    float* out = (float*)d_out;

    float *xa, *O, *h, *hf, *gb;
    cudaGetSymbolAddress((void**)&xa, g_xa);
    cudaGetSymbolAddress((void**)&O,  g_O);
    cudaGetSymbolAddress((void**)&h,  g_h);
    cudaGetSymbolAddress((void**)&hf, g_hf);
    cudaGetSymbolAddress((void**)&gb, g_gb);

    cudaFuncSetAttribute(attn_tc_kernel,
                         cudaFuncAttributeMaxDynamicSharedMemorySize,
                         AT_SMEM_BYTES);

    // 1) xa = rmsnorm(x) * norm1_w
    rmsnorm_kernel<<<M_, 128>>>(x, norm1_w, xa);

    // 2) qkv GEMM + pos add + split into Q/K/V [B,H,N,HD]
    gemm_tc_kernel<DIM_, MODE_QKV><<<dim3(3*DIM_/128, M_/128), 256>>>(
        xa, w_qkv, nullptr, pos, nullptr, nullptr);

    // 3) attention -> g_O [B,N,H*HD]
    attn_tc_kernel<<<dim3(N_/64, B_*H_), 128, AT_SMEM_BYTES>>>(mask);

    // 4) h = x + O @ w_proj^T + b_proj
    gemm_tc_kernel<DIM_, MODE_PROJ><<<dim3(DIM_/128, M_/128), 256>>>(
        O, w_proj, h, b_proj, x, nullptr);

    // 5) hf = rmsnorm(h) * norm2_w
    rmsnorm_kernel<<<M_, 128>>>(h, norm2_w, hf);

    // 6) g = silu(hf @ w1^T)
    gemm_tc_kernel<DIM_, MODE_SILU><<<dim3(HID_/128, M_/128), 256>>>(
        hf, w1, gb, nullptr, nullptr, nullptr);

    // 7) g *= hf @ w3^T
    gemm_tc_kernel<DIM_, MODE_MUL><<<dim3(HID_/128, M_/128), 256>>>(
        hf, w3, gb, nullptr, nullptr, nullptr);

    // 8) out = keep ? h + g @ w2^T : 0
    gemm_tc_kernel<HID_, MODE_FINAL><<<dim3(DIM_/128, M_/128), 256>>>(
        gb, w2, out, nullptr, h, npts);
}

// round 6
// speedup vs baseline: 3.0047x; 1.1285x over previous
#include <cuda_runtime.h>
#include <cstdint>

#define B_    4
#define N_    2048
#define DIM_  384
#define H_    8
#define HD_   48
#define HID_  1024
#define M_    (B_*N_)          // 8192
#define SCALE_ 0.14433756729740643f   // 48^-0.5
#define EPS_   1e-5f

// ---------------- scratch (no allocation allowed; __device__ globals) ----------
__device__ float g_xa [M_*DIM_];
__device__ float g_Q  [M_*DIM_];   // [B,H,N,HD]
__device__ float g_K  [M_*DIM_];
__device__ float g_V  [M_*DIM_];
__device__ float g_O  [M_*DIM_];   // [B,N,H*HD]
__device__ float g_h  [M_*DIM_];
__device__ float g_hf [M_*DIM_];
__device__ float g_gb [M_*HID_];

__device__ __forceinline__ uint32_t f2tf32(float f) {
    uint32_t u;
    asm("cvt.rna.tf32.f32 %0, %1;" : "=r"(u) : "f"(f));
    return u;
}

__device__ __forceinline__ void mma_tf32(float c[4], const uint32_t a[4], const uint32_t b[2]) {
    asm volatile(
        "mma.sync.aligned.m16n8k8.row.col.f32.tf32.tf32.f32 "
        "{%0,%1,%2,%3}, {%4,%5,%6,%7}, {%8,%9}, {%0,%1,%2,%3};"
        : "+f"(c[0]), "+f"(c[1]), "+f"(c[2]), "+f"(c[3])
        : "r"(a[0]), "r"(a[1]), "r"(a[2]), "r"(a[3]),
          "r"(b[0]), "r"(b[1]));
}

__device__ __forceinline__ uint32_t smem_u32(const void* p) {
    return (uint32_t)__cvta_generic_to_shared(p);
}
__device__ __forceinline__ void cp16(uint32_t dst, const void* src) {
    asm volatile("cp.async.cg.shared.global [%0], [%1], 16;" :: "r"(dst), "l"(src));
}
#define CP_COMMIT()  asm volatile("cp.async.commit_group;")
#define CP_WAIT(n)   asm volatile("cp.async.wait_group %0;" :: "n"(n))

// ---------------- RMSNorm: one row (384) per block of 128 threads --------------
__global__ void rmsnorm_kernel(const float* __restrict__ src,
                               const float* __restrict__ w,
                               float* __restrict__ dst) {
    const int row = blockIdx.x;
    const int tid = threadIdx.x;
    const float* xr = src + row*DIM_;
    float v0 = xr[tid], v1 = xr[tid+128], v2 = xr[tid+256];
    float s = v0*v0 + v1*v1 + v2*v2;
    #pragma unroll
    for (int o = 16; o > 0; o >>= 1) s += __shfl_xor_sync(0xffffffffu, s, o);
    __shared__ float red[4];
    if ((tid & 31) == 0) red[tid >> 5] = s;
    __syncthreads();
    float tot = red[0] + red[1] + red[2] + red[3];
    float sc = rsqrtf(tot * (1.0f/DIM_) + EPS_);
    float* dr = dst + row*DIM_;
    dr[tid]     = v0*sc*w[tid];
    dr[tid+128] = v1*sc*w[tid+128];
    dr[tid+256] = v2*sc*w[tid+256];
}

// ---------------- pipelined tf32 GEMM: C = A[M,K] * W[N,K]^T -------------------
// 128x128 tile, BK=16, 256 thr, 8 warps (2M x 4N), warp tile 64x32.
// cp.async 2-stage double buffer; smem [m][k] stride 20 (conflict-free frags).
// Raw fp32 bits fed to tf32 mma (hw truncation).
#define MODE_QKV   1
#define MODE_PROJ  2
#define MODE_FINAL 5

#define SSTR 20

template<int KDIM, int MODE>
__global__ void __launch_bounds__(256, 2) gemm_tc_kernel(
    const float* __restrict__ A, const float* __restrict__ W,
    float* __restrict__ C,
    const float* __restrict__ aux1,   // pos | b_proj | -
    const float* __restrict__ aux2,   // -   | x      | h
    const int* __restrict__ npts)
{
    __shared__ float As[2][128*SSTR];
    __shared__ float Bs[2][128*SSTR];

    const int tid  = threadIdx.x;
    const int bm   = blockIdx.y << 7;
    const int bn   = blockIdx.x << 7;
    const int warp = tid >> 5;
    const int wm   = (warp >> 2) * 64;
    const int wn   = (warp & 3) * 32;
    const int lane = tid & 31;
    const int gid  = lane >> 2;
    const int tg   = lane & 3;

    // load mapping: 512 chunks of 16B per matrix per stage; 2 per thread
    const int r0 = tid >> 2;              // rows tid/4 and tid/4+64
    const int c0 = (tid & 3) << 2;        // col offset 0,4,8,12

    float acc[4][4][4];
    #pragma unroll
    for (int mt = 0; mt < 4; mt++)
        #pragma unroll
        for (int nt = 0; nt < 4; nt++)
            #pragma unroll
            for (int e = 0; e < 4; e++) acc[mt][nt][e] = 0.f;

    const float* Ap0 = A + (long long)(bm + r0)*KDIM + c0;
    const float* Ap1 = Ap0 + (long long)64*KDIM;
    const float* Wp0 = W + (long long)(bn + r0)*KDIM + c0;
    const float* Wp1 = Wp0 + (long long)64*KDIM;
    const uint32_t dA0 = smem_u32(&As[0][r0*SSTR + c0]);
    const uint32_t dA1 = smem_u32(&As[0][(r0+64)*SSTR + c0]);
    const uint32_t dB0 = smem_u32(&Bs[0][r0*SSTR + c0]);
    const uint32_t dB1 = smem_u32(&Bs[0][(r0+64)*SSTR + c0]);
    const uint32_t stA = (uint32_t)(128*SSTR*4);   // byte offset between A stages
    const uint32_t stB = (uint32_t)(128*SSTR*4);

    auto load_stage = [&](int buf, int k0) {
        const uint32_t ob = buf ? stA : 0;
        cp16(dA0 + ob, Ap0 + k0);
        cp16(dA1 + ob, Ap1 + k0);
        cp16(dB0 + (buf ? stB : 0), Wp0 + k0);
        cp16(dB1 + (buf ? stB : 0), Wp1 + k0);
    };

    constexpr int NK = KDIM / 16;
    load_stage(0, 0);
    CP_COMMIT();

    int buf = 0;
    for (int kt = 0; kt < NK; kt++) {
        if (kt + 1 < NK) {
            load_stage(buf ^ 1, (kt + 1) * 16);
            CP_COMMIT();
            CP_WAIT(1);
        } else {
            CP_WAIT(0);
        }
        __syncthreads();

        const float* Ab = As[buf];
        const float* Bb = Bs[buf];
        #pragma unroll
        for (int ks = 0; ks < 2; ks++) {
            const int kb = ks << 3;
            uint32_t af[4][4];
            uint32_t bf[4][2];
            #pragma unroll
            for (int mt = 0; mt < 4; mt++) {
                const int m0 = wm + mt*16;
                af[mt][0] = __float_as_uint(Ab[(m0+gid  )*SSTR + kb+tg]);
                af[mt][1] = __float_as_uint(Ab[(m0+gid+8)*SSTR + kb+tg]);
                af[mt][2] = __float_as_uint(Ab[(m0+gid  )*SSTR + kb+tg+4]);
                af[mt][3] = __float_as_uint(Ab[(m0+gid+8)*SSTR + kb+tg+4]);
            }
            #pragma unroll
            for (int nt = 0; nt < 4; nt++) {
                const int n0 = wn + nt*8;
                bf[nt][0] = __float_as_uint(Bb[(n0+gid)*SSTR + kb+tg]);
                bf[nt][1] = __float_as_uint(Bb[(n0+gid)*SSTR + kb+tg+4]);
            }
            #pragma unroll
            for (int mt = 0; mt < 4; mt++)
                #pragma unroll
                for (int nt = 0; nt < 4; nt++)
                    mma_tf32(acc[mt][nt], af[mt], bf[nt]);
        }
        __syncthreads();
        buf ^= 1;
    }

    #pragma unroll
    for (int mt = 0; mt < 4; mt++) {
        #pragma unroll
        for (int nt = 0; nt < 4; nt++) {
            #pragma unroll
            for (int e = 0; e < 4; e++) {
                const int m = bm + wm + mt*16 + gid + ((e & 2) ? 8 : 0);
                const int n = bn + wn + nt*8 + tg*2 + (e & 1);
                float v = acc[mt][nt][e];
                if constexpr (MODE == MODE_QKV) {
                    const int b    = m >> 11;
                    const int ns   = m & 2047;
                    const int part = n / DIM_;
                    const int rem  = n - part*DIM_;
                    const int hh   = rem / HD_;
                    const int hd   = rem - hh*HD_;
                    if (part < 2) v += aux1[(b*N_ + ns)*HD_ + hd];
                    float* dst = (part == 0) ? g_Q : (part == 1 ? g_K : g_V);
                    dst[(((b << 3) + hh)*N_ + ns)*HD_ + hd] = v;
                } else if constexpr (MODE == MODE_PROJ) {
                    C[m*DIM_ + n] = v + aux1[n] + aux2[m*DIM_ + n];
                } else if constexpr (MODE == MODE_FINAL) {
                    const int np = npts[m >> 11];
                    C[m*DIM_ + n] = ((m & 2047) < np)
                                    ? (aux2[m*DIM_ + n] + v) : 0.0f;
                }
            }
        }
    }
}

// ---------------- fused GLU GEMM: C = silu(A w1^T) * (A w3^T) ------------------
// Same pipeline; A staged once, two B streams, two accumulator sets.
#define GLU_SMEM_BYTES (3 * 2 * 128 * SSTR * 4)

__global__ void __launch_bounds__(256, 1) gemm_glu_kernel(
    const float* __restrict__ A, const float* __restrict__ W1,
    const float* __restrict__ W3, float* __restrict__ C)
{
    extern __shared__ float gsm[];
    float* As = gsm;                       // [2][128*SSTR]
    float* B1 = gsm + 2*128*SSTR;
    float* B3 = gsm + 4*128*SSTR;

    const int tid  = threadIdx.x;
    const int bm   = blockIdx.y << 7;
    const int bn   = blockIdx.x << 7;
    const int warp = tid >> 5;
    const int wm   = (warp >> 2) * 64;
    const int wn   = (warp & 3) * 32;
    const int lane = tid & 31;
    const int gid  = lane >> 2;
    const int tg   = lane & 3;
    const int r0   = tid >> 2;
    const int c0   = (tid & 3) << 2;

    float acc1[4][4][4], acc3[4][4][4];
    #pragma unroll
    for (int mt = 0; mt < 4; mt++)
        #pragma unroll
        for (int nt = 0; nt < 4; nt++)
            #pragma unroll
            for (int e = 0; e < 4; e++) { acc1[mt][nt][e] = 0.f; acc3[mt][nt][e] = 0.f; }

    const float* Ap0 = A  + (long long)(bm + r0)*DIM_ + c0;
    const float* Ap1 = Ap0 + (long long)64*DIM_;
    const float* W1p0 = W1 + (long long)(bn + r0)*DIM_ + c0;
    const float* W1p1 = W1p0 + (long long)64*DIM_;
    const float* W3p0 = W3 + (long long)(bn + r0)*DIM_ + c0;
    const float* W3p1 = W3p0 + (long long)64*DIM_;
    const uint32_t dA0 = smem_u32(&As[r0*SSTR + c0]);
    const uint32_t dA1 = smem_u32(&As[(r0+64)*SSTR + c0]);
    const uint32_t d10 = smem_u32(&B1[r0*SSTR + c0]);
    const uint32_t d11 = smem_u32(&B1[(r0+64)*SSTR + c0]);
    const uint32_t d30 = smem_u32(&B3[r0*SSTR + c0]);
    const uint32_t d31 = smem_u32(&B3[(r0+64)*SSTR + c0]);
    const uint32_t st  = (uint32_t)(128*SSTR*4);

    auto load_stage = [&](int buf, int k0) {
        const uint32_t ob = buf ? st : 0;
        cp16(dA0 + ob, Ap0 + k0);
        cp16(dA1 + ob, Ap1 + k0);
        cp16(d10 + ob, W1p0 + k0);
        cp16(d11 + ob, W1p1 + k0);
        cp16(d30 + ob, W3p0 + k0);
        cp16(d31 + ob, W3p1 + k0);
    };

    constexpr int NK = DIM_ / 16;
    load_stage(0, 0);
    CP_COMMIT();

    int buf = 0;
    for (int kt = 0; kt < NK; kt++) {
        if (kt + 1 < NK) {
            load_stage(buf ^ 1, (kt + 1) * 16);
            CP_COMMIT();
            CP_WAIT(1);
        } else {
            CP_WAIT(0);
        }
        __syncthreads();

        const float* Ab  = As + buf*128*SSTR;
        const float* B1b = B1 + buf*128*SSTR;
        const float* B3b = B3 + buf*128*SSTR;
        #pragma unroll
        for (int ks = 0; ks < 2; ks++) {
            const int kb = ks << 3;
            uint32_t af[4][4];
            #pragma unroll
            for (int mt = 0; mt < 4; mt++) {
                const int m0 = wm + mt*16;
                af[mt][0] = __float_as_uint(Ab[(m0+gid  )*SSTR + kb+tg]);
                af[mt][1] = __float_as_uint(Ab[(m0+gid+8)*SSTR + kb+tg]);
                af[mt][2] = __float_as_uint(Ab[(m0+gid  )*SSTR + kb+tg+4]);
                af[mt][3] = __float_as_uint(Ab[(m0+gid+8)*SSTR + kb+tg+4]);
            }
            #pragma unroll
            for (int nt = 0; nt < 4; nt++) {
                const int n0 = wn + nt*8;
                uint32_t b1f[2], b3f[2];
                b1f[0] = __float_as_uint(B1b[(n0+gid)*SSTR + kb+tg]);
                b1f[1] = __float_as_uint(B1b[(n0+gid)*SSTR + kb+tg+4]);
                b3f[0] = __float_as_uint(B3b[(n0+gid)*SSTR + kb+tg]);
                b3f[1] = __float_as_uint(B3b[(n0+gid)*SSTR + kb+tg+4]);
                #pragma unroll
                for (int mt = 0; mt < 4; mt++) {
                    mma_tf32(acc1[mt][nt], af[mt], b1f);
                    mma_tf32(acc3[mt][nt], af[mt], b3f);
                }
            }
        }
        __syncthreads();
        buf ^= 1;
    }

    #pragma unroll
    for (int mt = 0; mt < 4; mt++) {
        #pragma unroll
        for (int nt = 0; nt < 4; nt++) {
            #pragma unroll
            for (int e = 0; e < 4; e++) {
                const int m = bm + wm + mt*16 + gid + ((e & 2) ? 8 : 0);
                const int n = bn + wn + nt*8 + tg*2 + (e & 1);
                const float v1 = acc1[mt][nt][e];
                const float v3 = acc3[mt][nt][e];
                C[m*HID_ + n] = (v1 / (1.0f + __expf(-v1))) * v3;
            }
        }
    }
}

// ---------------- tensor-core flash attention (unchanged from R4) ---------------
#define AT_KQ_W   (64*52)
#define AT_VT_W   (48*68)
#define AT_MS_W   (64*68)
#define AT_PS_W   (64*68)
#define AT_SMEM_BYTES ((AT_KQ_W + AT_VT_W + AT_MS_W + AT_PS_W) * 4)

__global__ void __launch_bounds__(128) attn_tc_kernel(const float* __restrict__ mask) {
    extern __shared__ uint32_t smw[];
    uint32_t* Ks = smw;                              // [64][52] (Q first, then K)
    uint32_t* Vt = smw + AT_KQ_W;                    // [48][68]
    float*    Ms = (float*)(smw + AT_KQ_W + AT_VT_W);// [64][68]
    uint32_t* Ps = smw + AT_KQ_W + AT_VT_W + AT_MS_W;// [64][68]

    const int bh  = blockIdx.y;
    const int b   = bh >> 3;
    const int hh  = bh & 7;
    const int q0  = blockIdx.x * 64;
    const int tid = threadIdx.x;
    const int warp = tid >> 5;
    const int lane = tid & 31;
    const int gid  = lane >> 2;
    const int tg   = lane & 3;
    const int m0   = warp * 16;

    const float4* Qsrc = (const float4*)(g_Q + ((long long)bh*N_ + q0)*HD_);
    for (int i = tid; i < 64*12; i += 128) {
        const int row = i / 12, c = i - row*12;
        float4 v = Qsrc[i];
        uint32_t* p = &Ks[row*52 + c*4];
        p[0] = f2tf32(v.x); p[1] = f2tf32(v.y);
        p[2] = f2tf32(v.z); p[3] = f2tf32(v.w);
    }
    __syncthreads();
    uint32_t qf[6][4];
    #pragma unroll
    for (int ks = 0; ks < 6; ks++) {
        const int kb = ks*8;
        qf[ks][0] = Ks[(m0+gid  )*52 + kb+tg];
        qf[ks][1] = Ks[(m0+gid+8)*52 + kb+tg];
        qf[ks][2] = Ks[(m0+gid  )*52 + kb+tg+4];
        qf[ks][3] = Ks[(m0+gid+8)*52 + kb+tg+4];
    }
    __syncthreads();

    float oacc[6][4];
    #pragma unroll
    for (int nt = 0; nt < 6; nt++)
        #pragma unroll
        for (int e = 0; e < 4; e++) oacc[nt][e] = 0.f;
    float mr0 = -1e30f, mr1 = -1e30f, lr0 = 0.f, lr1 = 0.f;

    const float* Kbase = g_K + (long long)bh*N_*HD_;
    const float* Vbase = g_V + (long long)bh*N_*HD_;
    const float* Mbase = mask + ((long long)b*N_ + q0)*N_;

    for (int kt = 0; kt < N_/64; kt++) {
        const int k0 = kt*64;
        const float4* Ksrc = (const float4*)(Kbase + k0*HD_);
        const float4* Vsrc = (const float4*)(Vbase + k0*HD_);
        for (int i = tid; i < 64*12; i += 128) {
            const int row = i / 12, c = i - row*12;
            float4 kv = Ksrc[i];
            uint32_t* p = &Ks[row*52 + c*4];
            p[0] = f2tf32(kv.x); p[1] = f2tf32(kv.y);
            p[2] = f2tf32(kv.z); p[3] = f2tf32(kv.w);
            float4 vv = Vsrc[i];
            Vt[(c*4+0)*68 + row] = f2tf32(vv.x);
            Vt[(c*4+1)*68 + row] = f2tf32(vv.y);
            Vt[(c*4+2)*68 + row] = f2tf32(vv.z);
            Vt[(c*4+3)*68 + row] = f2tf32(vv.w);
        }
        for (int i = tid; i < 64*16; i += 128) {
            const int row = i >> 4, c = (i & 15) << 2;
            *(float4*)&Ms[row*68 + c] =
                *(const float4*)(Mbase + (long long)row*N_ + k0 + c);
        }
        __syncthreads();

        float sacc[8][4];
        #pragma unroll
        for (int nt = 0; nt < 8; nt++)
            #pragma unroll
            for (int e = 0; e < 4; e++) sacc[nt][e] = 0.f;
        #pragma unroll
        for (int ks = 0; ks < 6; ks++) {
            const int kb = ks*8;
            uint32_t bf[8][2];
            #pragma unroll
            for (int nt = 0; nt < 8; nt++) {
                bf[nt][0] = Ks[(nt*8+gid)*52 + kb+tg];
                bf[nt][1] = Ks[(nt*8+gid)*52 + kb+tg+4];
            }
            #pragma unroll
            for (int nt = 0; nt < 8; nt++)
                mma_tf32(sacc[nt], qf[ks], bf[nt]);
        }

        float mx0 = mr0, mx1 = mr1;
        #pragma unroll
        for (int nt = 0; nt < 8; nt++) {
            const int col = nt*8 + tg*2;
            float v0 = sacc[nt][0]*SCALE_ + Ms[(m0+gid  )*68 + col];
            float v1 = sacc[nt][1]*SCALE_ + Ms[(m0+gid  )*68 + col+1];
            float v2 = sacc[nt][2]*SCALE_ + Ms[(m0+gid+8)*68 + col];
            float v3 = sacc[nt][3]*SCALE_ + Ms[(m0+gid+8)*68 + col+1];
            sacc[nt][0] = v0; sacc[nt][1] = v1; sacc[nt][2] = v2; sacc[nt][3] = v3;
            mx0 = fmaxf(mx0, fmaxf(v0, v1));
            mx1 = fmaxf(mx1, fmaxf(v2, v3));
        }
        mx0 = fmaxf(mx0, __shfl_xor_sync(0xffffffffu, mx0, 1));
        mx0 = fmaxf(mx0, __shfl_xor_sync(0xffffffffu, mx0, 2));
        mx1 = fmaxf(mx1, __shfl_xor_sync(0xffffffffu, mx1, 1));
        mx1 = fmaxf(mx1, __shfl_xor_sync(0xffffffffu, mx1, 2));
        const float a0 = __expf(mr0 - mx0);
        const float a1 = __expf(mr1 - mx1);
        mr0 = mx0; mr1 = mx1;
        lr0 *= a0;  lr1 *= a1;
        #pragma unroll
        for (int nt = 0; nt < 6; nt++) {
            oacc[nt][0] *= a0; oacc[nt][1] *= a0;
            oacc[nt][2] *= a1; oacc[nt][3] *= a1;
        }
        float ps0 = 0.f, ps1 = 0.f;
        #pragma unroll
        for (int nt = 0; nt < 8; nt++) {
            const int col = nt*8 + tg*2;
            float p0 = __expf(sacc[nt][0] - mx0);
            float p1 = __expf(sacc[nt][1] - mx0);
            float p2 = __expf(sacc[nt][2] - mx1);
            float p3 = __expf(sacc[nt][3] - mx1);
            ps0 += p0 + p1;
            ps1 += p2 + p3;
            Ps[(m0+gid  )*68 + col  ] = f2tf32(p0);
            Ps[(m0+gid  )*68 + col+1] = f2tf32(p1);
            Ps[(m0+gid+8)*68 + col  ] = f2tf32(p2);
            Ps[(m0+gid+8)*68 + col+1] = f2tf32(p3);
        }
        lr0 += ps0; lr1 += ps1;
        __syncwarp();

        #pragma unroll
        for (int ks = 0; ks < 8; ks++) {
            const int kb = ks*8;
            uint32_t af[4];
            af[0] = Ps[(m0+gid  )*68 + kb+tg];
            af[1] = Ps[(m0+gid+8)*68 + kb+tg];
            af[2] = Ps[(m0+gid  )*68 + kb+tg+4];
            af[3] = Ps[(m0+gid+8)*68 + kb+tg+4];
            #pragma unroll
            for (int nt = 0; nt < 6; nt++) {
                uint32_t bv[2];
                bv[0] = Vt[(nt*8+gid)*68 + kb+tg];
                bv[1] = Vt[(nt*8+gid)*68 + kb+tg+4];
                mma_tf32(oacc[nt], af, bv);
            }
        }
        __syncthreads();
    }

    lr0 += __shfl_xor_sync(0xffffffffu, lr0, 1);
    lr0 += __shfl_xor_sync(0xffffffffu, lr0, 2);
    lr1 += __shfl_xor_sync(0xffffffffu, lr1, 1);
    lr1 += __shfl_xor_sync(0xffffffffu, lr1, 2);
    const float i0 = 1.0f / lr0;
    const float i1 = 1.0f / lr1;

    const long long r0 = (long long)(b*N_ + q0 + m0 + gid)*DIM_ + hh*HD_;
    const long long r1 = r0 + 8LL*DIM_;
    #pragma unroll
    for (int nt = 0; nt < 6; nt++) {
        const int col = nt*8 + tg*2;
        *(float2*)&g_O[r0 + col] = make_float2(oacc[nt][0]*i0, oacc[nt][1]*i0);
        *(float2*)&g_O[r1 + col] = make_float2(oacc[nt][2]*i1, oacc[nt][3]*i1);
    }
}

// ---------------- launch ------------------------------------------------------
extern "C" void kernel_launch(void* const* d_in, const int* in_sizes, int n_in,
                              void* d_out, int out_size)
{
    const float* x       = (const float*)d_in[0];
    const float* pos     = (const float*)d_in[1];
    const float* mask    = (const float*)d_in[2];
    const int*   npts    = (const int*)d_in[3];   // int32 (jax canonicalized)
    const float* norm1_w = (const float*)d_in[4];
    const float* norm2_w = (const float*)d_in[5];
    const float* w_qkv   = (const float*)d_in[6];
    const float* w_proj  = (const float*)d_in[7];
    const float* b_proj  = (const float*)d_in[8];
    const float* w1      = (const float*)d_in[9];
    const float* w2      = (const float*)d_in[10];
    const float* w3      = (const float*)d_in[11];
    float* out = (float*)d_out;

    float *xa, *O, *h, *hf, *gb;
    cudaGetSymbolAddress((void**)&xa, g_xa);
    cudaGetSymbolAddress((void**)&O,  g_O);
    cudaGetSymbolAddress((void**)&h,  g_h);
    cudaGetSymbolAddress((void**)&hf, g_hf);
    cudaGetSymbolAddress((void**)&gb, g_gb);

    cudaFuncSetAttribute(attn_tc_kernel,
                         cudaFuncAttributeMaxDynamicSharedMemorySize,
                         AT_SMEM_BYTES);
    cudaFuncSetAttribute(gemm_glu_kernel,
                         cudaFuncAttributeMaxDynamicSharedMemorySize,
                         GLU_SMEM_BYTES);

    // 1) xa = rmsnorm(x) * norm1_w
    rmsnorm_kernel<<<M_, 128>>>(x, norm1_w, xa);

    // 2) qkv GEMM + pos add + split into Q/K/V [B,H,N,HD]
    gemm_tc_kernel<DIM_, MODE_QKV><<<dim3(3*DIM_/128, M_/128), 256>>>(
        xa, w_qkv, nullptr, pos, nullptr, nullptr);

    // 3) attention -> g_O [B,N,H*HD]
    attn_tc_kernel<<<dim3(N_/64, B_*H_), 128, AT_SMEM_BYTES>>>(mask);

    // 4) h = x + O @ w_proj^T + b_proj
    gemm_tc_kernel<DIM_, MODE_PROJ><<<dim3(DIM_/128, M_/128), 256>>>(
        O, w_proj, h, b_proj, x, nullptr);

    // 5) hf = rmsnorm(h) * norm2_w
    rmsnorm_kernel<<<M_, 128>>>(h, norm2_w, hf);

    // 6+7) g = silu(hf @ w1^T) * (hf @ w3^T)   (fused GLU)
    gemm_glu_kernel<<<dim3(HID_/128, M_/128), 256, GLU_SMEM_BYTES>>>(
        hf, w1, w3, gb);

    // 8) out = keep ? h + g @ w2^T : 0
    gemm_tc_kernel<HID_, MODE_FINAL><<<dim3(DIM_/128, M_/128), 256>>>(
        gb, w2, out, nullptr, h, npts);
}

// round 8
// speedup vs baseline: 4.1131x; 1.3689x over previous
#include <cuda_runtime.h>
#include <cstdint>

#define B_    4
#define N_    2048
#define DIM_  384
#define H_    8
#define HD_   48
#define HID_  1024
#define M_    (B_*N_)          // 8192
#define SCALE_ 0.14433756729740643f   // 48^-0.5
#define EPS_   1e-5f

// ---------------- scratch (no allocation allowed; __device__ globals) ----------
__device__ float g_xa [M_*DIM_];
__device__ float g_Q  [M_*DIM_];   // [B,H,N,HD]
__device__ float g_K  [M_*DIM_];
__device__ float g_V  [M_*DIM_];
__device__ float g_O  [M_*DIM_];   // [B,N,H*HD]
__device__ float g_h  [M_*DIM_];
__device__ float g_hf [M_*DIM_];
__device__ float g_gb [M_*HID_];

__device__ __forceinline__ void mma_tf32(float c[4], const uint32_t a[4], const uint32_t b[2]) {
    asm volatile(
        "mma.sync.aligned.m16n8k8.row.col.f32.tf32.tf32.f32 "
        "{%0,%1,%2,%3}, {%4,%5,%6,%7}, {%8,%9}, {%0,%1,%2,%3};"
        : "+f"(c[0]), "+f"(c[1]), "+f"(c[2]), "+f"(c[3])
        : "r"(a[0]), "r"(a[1]), "r"(a[2]), "r"(a[3]),
          "r"(b[0]), "r"(b[1]));
}

__device__ __forceinline__ uint32_t smem_u32(const void* p) {
    return (uint32_t)__cvta_generic_to_shared(p);
}
__device__ __forceinline__ void cp16(uint32_t dst, const void* src) {
    asm volatile("cp.async.cg.shared.global [%0], [%1], 16;" :: "r"(dst), "l"(src));
}
#define CP_COMMIT()  asm volatile("cp.async.commit_group;")
#define CP_WAIT(n)   asm volatile("cp.async.wait_group %0;" :: "n"(n))

// ---------------- RMSNorm: one row (384) per block of 128 threads --------------
__global__ void rmsnorm_kernel(const float* __restrict__ src,
                               const float* __restrict__ w,
                               float* __restrict__ dst) {
    const int row = blockIdx.x;
    const int tid = threadIdx.x;
    const float* xr = src + row*DIM_;
    float v0 = xr[tid], v1 = xr[tid+128], v2 = xr[tid+256];
    float s = v0*v0 + v1*v1 + v2*v2;
    #pragma unroll
    for (int o = 16; o > 0; o >>= 1) s += __shfl_xor_sync(0xffffffffu, s, o);
    __shared__ float red[4];
    if ((tid & 31) == 0) red[tid >> 5] = s;
    __syncthreads();
    float tot = red[0] + red[1] + red[2] + red[3];
    float sc = rsqrtf(tot * (1.0f/DIM_) + EPS_);
    float* dr = dst + row*DIM_;
    dr[tid]     = v0*sc*w[tid];
    dr[tid+128] = v1*sc*w[tid+128];
    dr[tid+256] = v2*sc*w[tid+256];
}

// ---------------- pipelined tf32 GEMM: C = A[M,K] * W[N,K]^T -------------------
#define MODE_QKV   1
#define MODE_PROJ  2
#define MODE_FINAL 5

#define SSTR 20

template<int KDIM, int MODE>
__global__ void __launch_bounds__(256, 2) gemm_tc_kernel(
    const float* __restrict__ A, const float* __restrict__ W,
    float* __restrict__ C,
    const float* __restrict__ aux1,   // pos | b_proj | -
    const float* __restrict__ aux2,   // -   | x      | h
    const int* __restrict__ npts)
{
    __shared__ float As[2][128*SSTR];
    __shared__ float Bs[2][128*SSTR];

    const int tid  = threadIdx.x;
    const int bm   = blockIdx.y << 7;
    const int bn   = blockIdx.x << 7;
    const int warp = tid >> 5;
    const int wm   = (warp >> 2) * 64;
    const int wn   = (warp & 3) * 32;
    const int lane = tid & 31;
    const int gid  = lane >> 2;
    const int tg   = lane & 3;

    const int r0 = tid >> 2;
    const int c0 = (tid & 3) << 2;

    float acc[4][4][4];
    #pragma unroll
    for (int mt = 0; mt < 4; mt++)
        #pragma unroll
        for (int nt = 0; nt < 4; nt++)
            #pragma unroll
            for (int e = 0; e < 4; e++) acc[mt][nt][e] = 0.f;

    const float* Ap0 = A + (long long)(bm + r0)*KDIM + c0;
    const float* Ap1 = Ap0 + (long long)64*KDIM;
    const float* Wp0 = W + (long long)(bn + r0)*KDIM + c0;
    const float* Wp1 = Wp0 + (long long)64*KDIM;
    const uint32_t dA0 = smem_u32(&As[0][r0*SSTR + c0]);
    const uint32_t dA1 = smem_u32(&As[0][(r0+64)*SSTR + c0]);
    const uint32_t dB0 = smem_u32(&Bs[0][r0*SSTR + c0]);
    const uint32_t dB1 = smem_u32(&Bs[0][(r0+64)*SSTR + c0]);
    const uint32_t st  = (uint32_t)(128*SSTR*4);

    auto load_stage = [&](int buf, int k0) {
        const uint32_t ob = buf ? st : 0;
        cp16(dA0 + ob, Ap0 + k0);
        cp16(dA1 + ob, Ap1 + k0);
        cp16(dB0 + ob, Wp0 + k0);
        cp16(dB1 + ob, Wp1 + k0);
    };

    constexpr int NK = KDIM / 16;
    load_stage(0, 0);
    CP_COMMIT();

    int buf = 0;
    for (int kt = 0; kt < NK; kt++) {
        if (kt + 1 < NK) {
            load_stage(buf ^ 1, (kt + 1) * 16);
            CP_COMMIT();
            CP_WAIT(1);
        } else {
            CP_WAIT(0);
        }
        __syncthreads();

        const float* Ab = As[buf];
        const float* Bb = Bs[buf];
        #pragma unroll
        for (int ks = 0; ks < 2; ks++) {
            const int kb = ks << 3;
            uint32_t af[4][4];
            uint32_t bf[4][2];
            #pragma unroll
            for (int mt = 0; mt < 4; mt++) {
                const int m0 = wm + mt*16;
                af[mt][0] = __float_as_uint(Ab[(m0+gid  )*SSTR + kb+tg]);
                af[mt][1] = __float_as_uint(Ab[(m0+gid+8)*SSTR + kb+tg]);
                af[mt][2] = __float_as_uint(Ab[(m0+gid  )*SSTR + kb+tg+4]);
                af[mt][3] = __float_as_uint(Ab[(m0+gid+8)*SSTR + kb+tg+4]);
            }
            #pragma unroll
            for (int nt = 0; nt < 4; nt++) {
                const int n0 = wn + nt*8;
                bf[nt][0] = __float_as_uint(Bb[(n0+gid)*SSTR + kb+tg]);
                bf[nt][1] = __float_as_uint(Bb[(n0+gid)*SSTR + kb+tg+4]);
            }
            #pragma unroll
            for (int mt = 0; mt < 4; mt++)
                #pragma unroll
                for (int nt = 0; nt < 4; nt++)
                    mma_tf32(acc[mt][nt], af[mt], bf[nt]);
        }
        __syncthreads();
        buf ^= 1;
    }

    #pragma unroll
    for (int mt = 0; mt < 4; mt++) {
        #pragma unroll
        for (int nt = 0; nt < 4; nt++) {
            #pragma unroll
            for (int e = 0; e < 4; e++) {
                const int m = bm + wm + mt*16 + gid + ((e & 2) ? 8 : 0);
                const int n = bn + wn + nt*8 + tg*2 + (e & 1);
                float v = acc[mt][nt][e];
                if constexpr (MODE == MODE_QKV) {
                    const int b    = m >> 11;
                    const int ns   = m & 2047;
                    const int part = n / DIM_;
                    const int rem  = n - part*DIM_;
                    const int hh   = rem / HD_;
                    const int hd   = rem - hh*HD_;
                    if (part < 2) v += aux1[(b*N_ + ns)*HD_ + hd];
                    float* dst = (part == 0) ? g_Q : (part == 1 ? g_K : g_V);
                    dst[(((b << 3) + hh)*N_ + ns)*HD_ + hd] = v;
                } else if constexpr (MODE == MODE_PROJ) {
                    C[m*DIM_ + n] = v + aux1[n] + aux2[m*DIM_ + n];
                } else if constexpr (MODE == MODE_FINAL) {
                    const int np = npts[m >> 11];
                    C[m*DIM_ + n] = ((m & 2047) < np)
                                    ? (aux2[m*DIM_ + n] + v) : 0.0f;
                }
            }
        }
    }
}

// ---------------- fused GLU GEMM: C = silu(A w1^T) * (A w3^T) ------------------
#define GLU_SMEM_BYTES (3 * 2 * 128 * SSTR * 4)

__global__ void __launch_bounds__(256, 1) gemm_glu_kernel(
    const float* __restrict__ A, const float* __restrict__ W1,
    const float* __restrict__ W3, float* __restrict__ C)
{
    extern __shared__ float gsm[];
    float* As = gsm;
    float* B1 = gsm + 2*128*SSTR;
    float* B3 = gsm + 4*128*SSTR;

    const int tid  = threadIdx.x;
    const int bm   = blockIdx.y << 7;
    const int bn   = blockIdx.x << 7;
    const int warp = tid >> 5;
    const int wm   = (warp >> 2) * 64;
    const int wn   = (warp & 3) * 32;
    const int lane = tid & 31;
    const int gid  = lane >> 2;
    const int tg   = lane & 3;
    const int r0   = tid >> 2;
    const int c0   = (tid & 3) << 2;

    float acc1[4][4][4], acc3[4][4][4];
    #pragma unroll
    for (int mt = 0; mt < 4; mt++)
        #pragma unroll
        for (int nt = 0; nt < 4; nt++)
            #pragma unroll
            for (int e = 0; e < 4; e++) { acc1[mt][nt][e] = 0.f; acc3[mt][nt][e] = 0.f; }

    const float* Ap0 = A  + (long long)(bm + r0)*DIM_ + c0;
    const float* Ap1 = Ap0 + (long long)64*DIM_;
    const float* W1p0 = W1 + (long long)(bn + r0)*DIM_ + c0;
    const float* W1p1 = W1p0 + (long long)64*DIM_;
    const float* W3p0 = W3 + (long long)(bn + r0)*DIM_ + c0;
    const float* W3p1 = W3p0 + (long long)64*DIM_;
    const uint32_t dA0 = smem_u32(&As[r0*SSTR + c0]);
    const uint32_t dA1 = smem_u32(&As[(r0+64)*SSTR + c0]);
    const uint32_t d10 = smem_u32(&B1[r0*SSTR + c0]);
    const uint32_t d11 = smem_u32(&B1[(r0+64)*SSTR + c0]);
    const uint32_t d30 = smem_u32(&B3[r0*SSTR + c0]);
    const uint32_t d31 = smem_u32(&B3[(r0+64)*SSTR + c0]);
    const uint32_t st  = (uint32_t)(128*SSTR*4);

    auto load_stage = [&](int buf, int k0) {
        const uint32_t ob = buf ? st : 0;
        cp16(dA0 + ob, Ap0 + k0);
        cp16(dA1 + ob, Ap1 + k0);
        cp16(d10 + ob, W1p0 + k0);
        cp16(d11 + ob, W1p1 + k0);
        cp16(d30 + ob, W3p0 + k0);
        cp16(d31 + ob, W3p1 + k0);
    };

    constexpr int NK = DIM_ / 16;
    load_stage(0, 0);
    CP_COMMIT();

    int buf = 0;
    for (int kt = 0; kt < NK; kt++) {
        if (kt + 1 < NK) {
            load_stage(buf ^ 1, (kt + 1) * 16);
            CP_COMMIT();
            CP_WAIT(1);
        } else {
            CP_WAIT(0);
        }
        __syncthreads();

        const float* Ab  = As + buf*128*SSTR;
        const float* B1b = B1 + buf*128*SSTR;
        const float* B3b = B3 + buf*128*SSTR;
        #pragma unroll
        for (int ks = 0; ks < 2; ks++) {
            const int kb = ks << 3;
            uint32_t af[4][4];
            #pragma unroll
            for (int mt = 0; mt < 4; mt++) {
                const int m0 = wm + mt*16;
                af[mt][0] = __float_as_uint(Ab[(m0+gid  )*SSTR + kb+tg]);
                af[mt][1] = __float_as_uint(Ab[(m0+gid+8)*SSTR + kb+tg]);
                af[mt][2] = __float_as_uint(Ab[(m0+gid  )*SSTR + kb+tg+4]);
                af[mt][3] = __float_as_uint(Ab[(m0+gid+8)*SSTR + kb+tg+4]);
            }
            #pragma unroll
            for (int nt = 0; nt < 4; nt++) {
                const int n0 = wn + nt*8;
                uint32_t b1f[2], b3f[2];
                b1f[0] = __float_as_uint(B1b[(n0+gid)*SSTR + kb+tg]);
                b1f[1] = __float_as_uint(B1b[(n0+gid)*SSTR + kb+tg+4]);
                b3f[0] = __float_as_uint(B3b[(n0+gid)*SSTR + kb+tg]);
                b3f[1] = __float_as_uint(B3b[(n0+gid)*SSTR + kb+tg+4]);
                #pragma unroll
                for (int mt = 0; mt < 4; mt++) {
                    mma_tf32(acc1[mt][nt], af[mt], b1f);
                    mma_tf32(acc3[mt][nt], af[mt], b3f);
                }
            }
        }
        __syncthreads();
        buf ^= 1;
    }

    #pragma unroll
    for (int mt = 0; mt < 4; mt++) {
        #pragma unroll
        for (int nt = 0; nt < 4; nt++) {
            #pragma unroll
            for (int e = 0; e < 4; e++) {
                const int m = bm + wm + mt*16 + gid + ((e & 2) ? 8 : 0);
                const int n = bn + wn + nt*8 + tg*2 + (e & 1);
                const float v1 = acc1[mt][nt][e];
                const float v3 = acc3[mt][nt][e];
                C[m*HID_ + n] = (v1 / (1.0f + __expf(-v1))) * v3;
            }
        }
    }
}

// ---------------- pipelined tensor-core flash attention ------------------------
// 128 thr (4 warps), q-tile 64, k-tile 64. K/V cp.async double-buffered (raw f32
// bits -> tf32 mma truncation). Mask read directly GMEM->regs (no reuse).
// Ps region aliases the Q staging region (Q frags are in regs after prologue).
#define AT_KSTR 52   // K & Q row stride: S-frag banks (20*gid+tg)%32 all-distinct
#define AT_VSTR 56   // V row stride: PV B-frag banks 8*{0,3,2,1}+gid all-distinct
#define AT_PSTR 68   // Ps row stride: A-frag banks (4*gid+tg) all-distinct
#define AT_PSQ_W (64*AT_PSTR)
#define AT_K_W   (64*AT_KSTR)
#define AT_V_W   (64*AT_VSTR)
#define AT_SMEM_BYTES ((AT_PSQ_W + 2*AT_K_W + 2*AT_V_W) * 4)

__global__ void __launch_bounds__(128, 3) attn_tc_kernel(const float* __restrict__ mask) {
    extern __shared__ float sm[];
    float* PsQ = sm;                    // Q staging (stride 52), later Ps (stride 68)
    float* Kd  = sm + AT_PSQ_W;         // 2 x [64][52]
    float* Vd  = Kd + 2*AT_K_W;         // 2 x [64][56]

    const int bh  = blockIdx.y;
    const int b   = bh >> 3;
    const int hh  = bh & 7;
    const int q0  = blockIdx.x * 64;
    const int tid = threadIdx.x;
    const int warp = tid >> 5;
    const int lane = tid & 31;
    const int gid  = lane >> 2;
    const int tg   = lane & 3;
    const int m0   = warp * 16;

    // ---- stage Q (cp.async, raw f32) ----
    const float* Qbase = g_Q + ((long long)bh*N_ + q0)*HD_;
    const uint32_t qdst = smem_u32(PsQ);
    for (int i = tid; i < 64*12; i += 128) {
        const int row = i / 12, c = i - row*12;
        cp16(qdst + (uint32_t)(row*AT_KSTR + c*4)*4, Qbase + row*HD_ + c*4);
    }
    CP_COMMIT();

    const float* Kbase = g_K + (long long)bh*N_*HD_;
    const float* Vbase = g_V + (long long)bh*N_*HD_;
    const uint32_t kdst = smem_u32(Kd);
    const uint32_t vdst = smem_u32(Vd);

    auto load_tile = [&](int bufi, int k0) {
        const uint32_t kb = kdst + (uint32_t)(bufi*AT_K_W)*4;
        const uint32_t vb = vdst + (uint32_t)(bufi*AT_V_W)*4;
        for (int i = tid; i < 64*12; i += 128) {
            const int row = i / 12, c = i - row*12;
            cp16(kb + (uint32_t)(row*AT_KSTR + c*4)*4, Kbase + (k0+row)*HD_ + c*4);
            cp16(vb + (uint32_t)(row*AT_VSTR + c*4)*4, Vbase + (k0+row)*HD_ + c*4);
        }
    };

    load_tile(0, 0);
    CP_COMMIT();

    // wait for Q (allow tile-0 group outstanding), pull Q frags to regs
    CP_WAIT(1);
    __syncthreads();
    uint32_t qf[6][4];
    #pragma unroll
    for (int ks = 0; ks < 6; ks++) {
        const int kb = ks*8;
        qf[ks][0] = __float_as_uint(PsQ[(m0+gid  )*AT_KSTR + kb+tg]);
        qf[ks][1] = __float_as_uint(PsQ[(m0+gid+8)*AT_KSTR + kb+tg]);
        qf[ks][2] = __float_as_uint(PsQ[(m0+gid  )*AT_KSTR + kb+tg+4]);
        qf[ks][3] = __float_as_uint(PsQ[(m0+gid+8)*AT_KSTR + kb+tg+4]);
    }
    __syncthreads();   // everyone has Q before Ps overwrites the region

    float oacc[6][4];
    #pragma unroll
    for (int nt = 0; nt < 6; nt++)
        #pragma unroll
        for (int e = 0; e < 4; e++) oacc[nt][e] = 0.f;
    float mr0 = -1e30f, mr1 = -1e30f, lr0 = 0.f, lr1 = 0.f;

    const float* Mr0 = mask + (long long)(b*N_ + q0 + m0 + gid)*N_;
    const float* Mr1 = Mr0 + 8LL*N_;

    int buf = 0;
    for (int kt = 0; kt < N_/64; kt++) {
        const int k0 = kt*64;
        if (kt + 1 < N_/64) {
            load_tile(buf ^ 1, k0 + 64);
            CP_COMMIT();
            CP_WAIT(1);
        } else {
            CP_WAIT(0);
        }
        __syncthreads();

        const float* Kb = Kd + buf*AT_K_W;
        const float* Vb = Vd + buf*AT_V_W;

        // prefetch mask pairs for this tile (consumed after S mma)
        float2 mv0[8], mv1[8];
        #pragma unroll
        for (int nt = 0; nt < 8; nt++) {
            mv0[nt] = *(const float2*)(Mr0 + k0 + nt*8 + tg*2);
            mv1[nt] = *(const float2*)(Mr1 + k0 + nt*8 + tg*2);
        }

        // ---- S = Q . K^T ----
        float sacc[8][4];
        #pragma unroll
        for (int nt = 0; nt < 8; nt++)
            #pragma unroll
            for (int e = 0; e < 4; e++) sacc[nt][e] = 0.f;
        #pragma unroll
        for (int ks = 0; ks < 6; ks++) {
            const int kb = ks*8;
            uint32_t bf[8][2];
            #pragma unroll
            for (int nt = 0; nt < 8; nt++) {
                bf[nt][0] = __float_as_uint(Kb[(nt*8+gid)*AT_KSTR + kb+tg]);
                bf[nt][1] = __float_as_uint(Kb[(nt*8+gid)*AT_KSTR + kb+tg+4]);
            }
            #pragma unroll
            for (int nt = 0; nt < 8; nt++)
                mma_tf32(sacc[nt], qf[ks], bf[nt]);
        }

        // ---- online softmax ----
        float mx0 = mr0, mx1 = mr1;
        #pragma unroll
        for (int nt = 0; nt < 8; nt++) {
            float v0 = sacc[nt][0]*SCALE_ + mv0[nt].x;
            float v1 = sacc[nt][1]*SCALE_ + mv0[nt].y;
            float v2 = sacc[nt][2]*SCALE_ + mv1[nt].x;
            float v3 = sacc[nt][3]*SCALE_ + mv1[nt].y;
            sacc[nt][0] = v0; sacc[nt][1] = v1; sacc[nt][2] = v2; sacc[nt][3] = v3;
            mx0 = fmaxf(mx0, fmaxf(v0, v1));
            mx1 = fmaxf(mx1, fmaxf(v2, v3));
        }
        mx0 = fmaxf(mx0, __shfl_xor_sync(0xffffffffu, mx0, 1));
        mx0 = fmaxf(mx0, __shfl_xor_sync(0xffffffffu, mx0, 2));
        mx1 = fmaxf(mx1, __shfl_xor_sync(0xffffffffu, mx1, 1));
        mx1 = fmaxf(mx1, __shfl_xor_sync(0xffffffffu, mx1, 2));
        const float a0 = __expf(mr0 - mx0);
        const float a1 = __expf(mr1 - mx1);
        mr0 = mx0; mr1 = mx1;
        lr0 *= a0;  lr1 *= a1;
        #pragma unroll
        for (int nt = 0; nt < 6; nt++) {
            oacc[nt][0] *= a0; oacc[nt][1] *= a0;
            oacc[nt][2] *= a1; oacc[nt][3] *= a1;
        }
        float ps0 = 0.f, ps1 = 0.f;
        #pragma unroll
        for (int nt = 0; nt < 8; nt++) {
            const int col = nt*8 + tg*2;
            float p0 = __expf(sacc[nt][0] - mx0);
            float p1 = __expf(sacc[nt][1] - mx0);
            float p2 = __expf(sacc[nt][2] - mx1);
            float p3 = __expf(sacc[nt][3] - mx1);
            ps0 += p0 + p1;
            ps1 += p2 + p3;
            PsQ[(m0+gid  )*AT_PSTR + col  ] = p0;
            PsQ[(m0+gid  )*AT_PSTR + col+1] = p1;
            PsQ[(m0+gid+8)*AT_PSTR + col  ] = p2;
            PsQ[(m0+gid+8)*AT_PSTR + col+1] = p3;
        }
        lr0 += ps0; lr1 += ps1;
        __syncwarp();   // Ps rows are per-warp private

        // ---- O += P . V ----
        #pragma unroll
        for (int ks = 0; ks < 8; ks++) {
            const int kb = ks*8;
            uint32_t af[4];
            af[0] = __float_as_uint(PsQ[(m0+gid  )*AT_PSTR + kb+tg]);
            af[1] = __float_as_uint(PsQ[(m0+gid+8)*AT_PSTR + kb+tg]);
            af[2] = __float_as_uint(PsQ[(m0+gid  )*AT_PSTR + kb+tg+4]);
            af[3] = __float_as_uint(PsQ[(m0+gid+8)*AT_PSTR + kb+tg+4]);
            #pragma unroll
            for (int nt = 0; nt < 6; nt++) {
                uint32_t bv[2];
                bv[0] = __float_as_uint(Vb[(kb+tg  )*AT_VSTR + nt*8+gid]);
                bv[1] = __float_as_uint(Vb[(kb+tg+4)*AT_VSTR + nt*8+gid]);
                mma_tf32(oacc[nt], af, bv);
            }
        }
        __syncthreads();   // done reading buf before next iter overwrites it
        buf ^= 1;
    }

    lr0 += __shfl_xor_sync(0xffffffffu, lr0, 1);
    lr0 += __shfl_xor_sync(0xffffffffu, lr0, 2);
    lr1 += __shfl_xor_sync(0xffffffffu, lr1, 1);
    lr1 += __shfl_xor_sync(0xffffffffu, lr1, 2);
    const float i0 = 1.0f / lr0;
    const float i1 = 1.0f / lr1;

    const long long r0 = (long long)(b*N_ + q0 + m0 + gid)*DIM_ + hh*HD_;
    const long long r1 = r0 + 8LL*DIM_;
    #pragma unroll
    for (int nt = 0; nt < 6; nt++) {
        const int col = nt*8 + tg*2;
        *(float2*)&g_O[r0 + col] = make_float2(oacc[nt][0]*i0, oacc[nt][1]*i0);
        *(float2*)&g_O[r1 + col] = make_float2(oacc[nt][2]*i1, oacc[nt][3]*i1);
    }
}

// ---------------- launch ------------------------------------------------------
extern "C" void kernel_launch(void* const* d_in, const int* in_sizes, int n_in,
                              void* d_out, int out_size)
{
    const float* x       = (const float*)d_in[0];
    const float* pos     = (const float*)d_in[1];
    const float* mask    = (const float*)d_in[2];
    const int*   npts    = (const int*)d_in[3];   // int32 (jax canonicalized)
    const float* norm1_w = (const float*)d_in[4];
    const float* norm2_w = (const float*)d_in[5];
    const float* w_qkv   = (const float*)d_in[6];
    const float* w_proj  = (const float*)d_in[7];
    const float* b_proj  = (const float*)d_in[8];
    const float* w1      = (const float*)d_in[9];
    const float* w2      = (const float*)d_in[10];
    const float* w3      = (const float*)d_in[11];
    float* out = (float*)d_out;

    float *xa, *O, *h, *hf, *gb;
    cudaGetSymbolAddress((void**)&xa, g_xa);
    cudaGetSymbolAddress((void**)&O,  g_O);
    cudaGetSymbolAddress((void**)&h,  g_h);
    cudaGetSymbolAddress((void**)&hf, g_hf);
    cudaGetSymbolAddress((void**)&gb, g_gb);

    cudaFuncSetAttribute(attn_tc_kernel,
                         cudaFuncAttributeMaxDynamicSharedMemorySize,
                         AT_SMEM_BYTES);
    cudaFuncSetAttribute(gemm_glu_kernel,
                         cudaFuncAttributeMaxDynamicSharedMemorySize,
                         GLU_SMEM_BYTES);

    // 1) xa = rmsnorm(x) * norm1_w
    rmsnorm_kernel<<<M_, 128>>>(x, norm1_w, xa);

    // 2) qkv GEMM + pos add + split into Q/K/V [B,H,N,HD]
    gemm_tc_kernel<DIM_, MODE_QKV><<<dim3(3*DIM_/128, M_/128), 256>>>(
        xa, w_qkv, nullptr, pos, nullptr, nullptr);

    // 3) attention -> g_O [B,N,H*HD]
    attn_tc_kernel<<<dim3(N_/64, B_*H_), 128, AT_SMEM_BYTES>>>(mask);

    // 4) h = x + O @ w_proj^T + b_proj
    gemm_tc_kernel<DIM_, MODE_PROJ><<<dim3(DIM_/128, M_/128), 256>>>(
        O, w_proj, h, b_proj, x, nullptr);

    // 5) hf = rmsnorm(h) * norm2_w
    rmsnorm_kernel<<<M_, 128>>>(h, norm2_w, hf);

    // 6+7) g = silu(hf @ w1^T) * (hf @ w3^T)   (fused GLU)
    gemm_glu_kernel<<<dim3(HID_/128, M_/128), 256, GLU_SMEM_BYTES>>>(
        hf, w1, w3, gb);

    // 8) out = keep ? h + g @ w2^T : 0
    gemm_tc_kernel<HID_, MODE_FINAL><<<dim3(DIM_/128, M_/128), 256>>>(
        gb, w2, out, nullptr, h, npts);
}